// round 2
// baseline (speedup 1.0000x reference)
#include <cuda_runtime.h>
#include <math.h>

#define TT 8192
#define AA 128
#define NBCOV 128   // cov partial chunks (64 rows each)

// ---------------- scratch (static device globals; no allocation) ----------------
__device__ float g_covpart[NBCOV][AA*AA];   // 8.4 MB
__device__ float g_colpart[NBCOV][AA];
__device__ float g_cov[AA*AA];
__device__ float g_colsum[AA];
__device__ float g_corr[AA*AA];
__device__ float g_eig0[AA*AA];
__device__ float g_eig1[AA*AA];
__device__ float g_rowsum[AA];
__device__ float g_rowabs[AA];
__device__ float g_rowsq[AA];
__device__ float g_fp0[16];
__device__ float g_fp1[16];
__device__ float g_roll20[TT];
__device__ float g_roll10[TT];
__device__ float g_csstd[TT];
__device__ float g_conc[TT];

struct ScalarsT {
    double sum_cs, sum_conc, sum_r10, sum_last5, sum_rowsum, sum_rowabs, cnt20;
};
__device__ ScalarsT g_s;

// ---------------- helpers ----------------
__device__ __forceinline__ float warpReduceAdd(float v) {
    #pragma unroll
    for (int o = 16; o; o >>= 1) v += __shfl_xor_sync(0xffffffffu, v, o);
    return v;
}

__device__ __forceinline__ double blockReduceAddD(double v, double* sh) {
    int tid = threadIdx.x;
    sh[tid] = v; __syncthreads();
    for (int s = blockDim.x >> 1; s; s >>= 1) {
        if (tid < (int)s) sh[tid] += sh[tid + s];
        __syncthreads();
    }
    double r = sh[0]; __syncthreads();
    return r;
}

// ---------------- per-row stats: cross-sectional std (ddof=1) + sign concordance ----------------
__global__ void rowstats_kernel(const float* __restrict__ x) {
    int wid = threadIdx.x >> 5, lane = threadIdx.x & 31;
    int gw = blockIdx.x * 8 + wid;
    #pragma unroll
    for (int rr = 0; rr < 4; rr++) {
        int r = gw * 4 + rr;
        float4 v = reinterpret_cast<const float4*>(x + (size_t)r * AA)[lane];
        float s = v.x + v.y + v.z + v.w;
        float q = v.x*v.x + v.y*v.y + v.z*v.z + v.w*v.w;
        float p = ((v.x > 0.f)?1.f:0.f) + ((v.y > 0.f)?1.f:0.f) + ((v.z > 0.f)?1.f:0.f) + ((v.w > 0.f)?1.f:0.f);
        float n = ((v.x < 0.f)?1.f:0.f) + ((v.y < 0.f)?1.f:0.f) + ((v.z < 0.f)?1.f:0.f) + ((v.w < 0.f)?1.f:0.f);
        s = warpReduceAdd(s); q = warpReduceAdd(q);
        p = warpReduceAdd(p); n = warpReduceAdd(n);
        if (lane == 0) {
            float var = (q - s * s * (1.0f/AA)) * (1.0f/(AA-1));
            g_csstd[r] = sqrtf(fmaxf(var, 0.f));
            float z = (float)AA - p - n;
            g_conc[r] = p*p + n*n + z*z;   // exact small ints
        }
    }
}

// ---------------- Gram partials: g_covpart[b] = X_chunk^T X_chunk (uncentered) + column sums ----------------
__global__ void covpart_kernel(const float* __restrict__ x) {
    __shared__ float tile[64 * AA];   // 32 KB
    int tid = threadIdx.x;
    const float4* src = reinterpret_cast<const float4*>(x + (size_t)blockIdx.x * 64 * AA);
    float4* dst = reinterpret_cast<float4*>(tile);
    #pragma unroll
    for (int k = 0; k < 8; k++) dst[tid + 256*k] = src[tid + 256*k];
    __syncthreads();

    int ti = tid >> 4, tj = tid & 15;
    int i0 = ti * 8, j0 = tj * 8;
    float acc[8][8] = {};
    for (int t = 0; t < 64; t++) {
        float a[8], b[8];
        *reinterpret_cast<float4*>(a)     = *reinterpret_cast<float4*>(&tile[t*AA + i0]);
        *reinterpret_cast<float4*>(a + 4) = *reinterpret_cast<float4*>(&tile[t*AA + i0 + 4]);
        *reinterpret_cast<float4*>(b)     = *reinterpret_cast<float4*>(&tile[t*AA + j0]);
        *reinterpret_cast<float4*>(b + 4) = *reinterpret_cast<float4*>(&tile[t*AA + j0 + 4]);
        #pragma unroll
        for (int ii = 0; ii < 8; ii++)
            #pragma unroll
            for (int jj = 0; jj < 8; jj++)
                acc[ii][jj] = fmaf(a[ii], b[jj], acc[ii][jj]);
    }
    float* outp = g_covpart[blockIdx.x];
    #pragma unroll
    for (int ii = 0; ii < 8; ii++)
        #pragma unroll
        for (int jj = 0; jj < 8; jj++)
            outp[(i0+ii)*AA + (j0+jj)] = acc[ii][jj];

    if (tid < AA) {  // column sums of this chunk (tile only read, no sync needed)
        float cs = 0.f;
        for (int t = 0; t < 64; t++) cs += tile[t*AA + tid];
        g_colpart[blockIdx.x][tid] = cs;
    }
}

// ---------------- reduce partials ----------------
__global__ void covreduce_kernel() {
    if (blockIdx.x < 64) {
        int idx = blockIdx.x * 256 + threadIdx.x;
        float s = 0.f;
        for (int b = 0; b < NBCOV; b++) s += g_covpart[b][idx];
        g_cov[idx] = s;
    } else if (threadIdx.x < AA) {
        float s = 0.f;
        for (int b = 0; b < NBCOV; b++) s += g_colpart[b][threadIdx.x];
        g_colsum[threadIdx.x] = s;
    }
}

// ---------------- normalize to corr; per-row Σoffdiag, Σ|c|, Σc² ----------------
__global__ void corr_kernel() {
    __shared__ float invd[AA];
    __shared__ float colv[AA];
    __shared__ float red[AA];
    int j = threadIdx.x, i = blockIdx.x;
    float csj = g_colsum[j];
    colv[j] = csj;
    float dj = g_cov[j*AA + j] - csj * csj * (1.0f/TT);
    invd[j] = rsqrtf(dj);
    __syncthreads();
    float covij = g_cov[i*AA + j] - colv[i] * csj * (1.0f/TT);
    float c = covij * invd[i] * invd[j];
    g_corr[i*AA + j] = c;

    float coff = (i == j) ? 0.f : c;
    red[j] = coff; __syncthreads();
    for (int s = 64; s; s >>= 1) { if (j < s) red[j] += red[j+s]; __syncthreads(); }
    if (j == 0) g_rowsum[i] = red[0];
    __syncthreads();
    red[j] = fabsf(c); __syncthreads();
    for (int s = 64; s; s >>= 1) { if (j < s) red[j] += red[j+s]; __syncthreads(); }
    if (j == 0) g_rowabs[i] = red[0];
    __syncthreads();
    red[j] = c * c; __syncthreads();
    for (int s = 64; s; s >>= 1) { if (j < s) red[j] += red[j+s]; __syncthreads(); }
    if (j == 0) g_rowsq[i] = red[0];
}

// ---------------- one matrix squaring step with deferred Frobenius normalization ----------------
__global__ void square_kernel(int first, int sin, int sout) {
    __shared__ float shrow[8 * AA];
    __shared__ float red[AA];
    int j = threadIdx.x;
    const float* in  = first ? g_corr  : (sin == 0 ? g_eig0 : g_eig1);
    const float* fpp = first ? g_rowsq : (sin == 0 ? g_fp0  : g_fp1);
    int fpn = first ? AA : 16;
    float fr = 0.f;
    for (int k = 0; k < fpn; k++) fr += fpp[k];
    float s2 = 1.0f / fr;   // (1/frob)^2 applied to B·B

    int r0 = blockIdx.x * 8;
    #pragma unroll
    for (int r = 0; r < 8; r++) shrow[r*AA + j] = in[(r0 + r)*AA + j];
    __syncthreads();
    float acc[8] = {0,0,0,0,0,0,0,0};
    #pragma unroll 4
    for (int k = 0; k < AA; k++) {
        float bk = in[k*AA + j];
        #pragma unroll
        for (int r = 0; r < 8; r++) acc[r] = fmaf(shrow[r*AA + k], bk, acc[r]);
    }
    float* outb = (sout == 0) ? g_eig0 : g_eig1;
    float ps = 0.f;
    #pragma unroll
    for (int r = 0; r < 8; r++) {
        float v = acc[r] * s2;
        outb[(r0 + r)*AA + j] = v;
        ps += v * v;
    }
    red[j] = ps; __syncthreads();
    for (int s = 64; s; s >>= 1) { if (j < s) red[j] += red[j+s]; __syncthreads(); }
    if (j == 0) ((sout == 0) ? g_fp0 : g_fp1)[blockIdx.x] = red[0];
}

// ---------------- rolling off-diagonal correlation via  C.sum = Σ_t (Σ_a z_a)^2 ----------------
template<int W, int NWIN>
__global__ void rolling_kernel(const float* __restrict__ x) {
    __shared__ float sh[(63 + W) * AA];
    float* out = (W == 20) ? g_roll20 : g_roll10;
    const int ROWS = 63 + W;
    int base = blockIdx.x * 64;
    for (int idx = threadIdx.x; idx < ROWS * AA; idx += 256) {
        int r = idx >> 7, c = idx & 127;
        int gr = base + r;
        sh[idx] = (gr < TT) ? x[(size_t)gr * AA + c] : 0.f;
    }
    __syncthreads();
    int wid = threadIdx.x >> 5, lane = threadIdx.x & 31;
    for (int q = 0; q < 8; q++) {
        int lw = wid * 8 + q;
        int widx = base + lw;
        if (widx >= NWIN) break;           // uniform per warp
        float S0=0,S1=0,S2=0,S3=0,Q0=0,Q1=0,Q2=0,Q3=0;
        #pragma unroll 5
        for (int t = 0; t < W; t++) {
            const float* row = sh + (lw + t) * AA + lane;
            float v0 = row[0], v1 = row[32], v2 = row[64], v3 = row[96];
            S0 += v0; Q0 = fmaf(v0, v0, Q0);
            S1 += v1; Q1 = fmaf(v1, v1, Q1);
            S2 += v2; Q2 = fmaf(v2, v2, Q2);
            S3 += v3; Q3 = fmaf(v3, v3, Q3);
        }
        const float iw = 1.0f / W;
        float i0 = rsqrtf(Q0 - S0*S0*iw);
        float i1 = rsqrtf(Q1 - S1*S1*iw);
        float i2 = rsqrtf(Q2 - S2*S2*iw);
        float i3 = rsqrtf(Q3 - S3*S3*iw);
        float part = S0*iw*i0 + S1*iw*i1 + S2*iw*i2 + S3*iw*i3;
        part = warpReduceAdd(part);        // Σ_a mean_a * invd_a
        float acc = 0.f;
        #pragma unroll 5
        for (int t = 0; t < W; t++) {
            const float* row = sh + (lw + t) * AA + lane;
            float p = row[0]*i0 + row[32]*i1 + row[64]*i2 + row[96]*i3;
            p = warpReduceAdd(p);
            float s = p - part;            // Σ_a z_a(t)
            acc = fmaf(s, s, acc);
        }
        if (lane == 0) out[widx] = (acc - (float)AA) * (1.0f/16256.0f);
    }
}

// ---------------- scalar reductions (fp64 to protect sign-sensitive branches) ----------------
__global__ void scalars_kernel() {
    __shared__ double sd[256];
    int tid = threadIdx.x;
    double a;
    a = 0; for (int i = tid; i < TT; i += 256) a += (double)g_csstd[i];
    double sum_cs = blockReduceAddD(a, sd);
    a = 0; for (int i = tid; i < TT; i += 256) a += (double)g_conc[i];
    double sum_conc = blockReduceAddD(a, sd);
    a = 0; for (int i = tid; i < TT-20; i += 256) a += (g_roll20[i] > 0.7f) ? 1.0 : 0.0;
    double cnt20 = blockReduceAddD(a, sd);
    a = 0; for (int i = tid; i < TT-10; i += 256) a += (double)g_roll10[i];
    double sum_r10 = blockReduceAddD(a, sd);
    a = (tid < AA) ? (double)g_rowsum[tid] : 0.0;
    double sum_rowsum = blockReduceAddD(a, sd);
    a = (tid < AA) ? (double)g_rowabs[tid] : 0.0;
    double sum_rowabs = blockReduceAddD(a, sd);
    if (tid == 0) {
        double l5 = 0;
        for (int i = TT - 10 - 5; i < TT - 10; i++) l5 += (double)g_roll10[i];
        g_s.sum_cs = sum_cs; g_s.sum_conc = sum_conc; g_s.cnt20 = cnt20;
        g_s.sum_r10 = sum_r10; g_s.sum_last5 = l5;
        g_s.sum_rowsum = sum_rowsum; g_s.sum_rowabs = sum_rowabs;
    }
}

// ---------------- Rayleigh quotient + MLP + assembly ----------------
__global__ void final_kernel(const float* __restrict__ x, const float* __restrict__ pos,
        const float* __restrict__ w1, const float* __restrict__ b1,
        const float* __restrict__ gam, const float* __restrict__ bet,
        const float* __restrict__ w2, const float* __restrict__ b2,
        const float* __restrict__ w3, const float* __restrict__ b3,
        float* __restrict__ out, int fsel) {
    __shared__ float feats[2*AA];
    __shared__ float h1[AA];
    __shared__ float h2[64];
    __shared__ float vvec[AA];
    __shared__ float rf[AA];
    __shared__ int ri[AA];
    __shared__ double rd[AA];
    int j = threadIdx.x;   // 128 threads
    const float* Bf = (fsel == 0) ? g_eig0 : g_eig1;

    feats[j] = x[(size_t)(TT-1)*AA + j];
    feats[AA + j] = pos[j];

    // dominant eigvec: column of converged B^(4096) at max diag
    rf[j] = Bf[j*AA + j]; ri[j] = j;
    __syncthreads();
    for (int s = 64; s; s >>= 1) {
        if (j < s && rf[j+s] > rf[j]) { rf[j] = rf[j+s]; ri[j] = ri[j+s]; }
        __syncthreads();
    }
    int jstar = ri[0];
    __syncthreads();
    vvec[j] = Bf[jstar*AA + j];
    __syncthreads();
    float y = 0.f;
    for (int k = 0; k < AA; k++) y = fmaf(g_corr[j*AA + k], vvec[k], y);
    rd[j] = (double)vvec[j] * (double)y; __syncthreads();
    for (int s = 64; s; s >>= 1) { if (j < s) rd[j] += rd[j+s]; __syncthreads(); }
    double num = rd[0]; __syncthreads();
    rd[j] = (double)vvec[j] * (double)vvec[j]; __syncthreads();
    for (int s = 64; s; s >>= 1) { if (j < s) rd[j] += rd[j+s]; __syncthreads(); }
    double den = rd[0]; __syncthreads();

    // position diversity
    float pa = fabsf(pos[j]);
    rd[j] = (double)pa; __syncthreads();
    for (int s = 64; s; s >>= 1) { if (j < s) rd[j] += rd[j+s]; __syncthreads(); }
    double psum = rd[0]; __syncthreads();
    rf[j] = pa; __syncthreads();
    for (int s = 64; s; s >>= 1) { if (j < s) rf[j] = fmaxf(rf[j], rf[j+s]); __syncthreads(); }
    float pmax = rf[0]; __syncthreads();

    // MLP
    float s1 = b1[j];
    for (int k = 0; k < 2*AA; k++) s1 = fmaf(feats[k], w1[k*AA + j], s1);
    s1 = fmaxf(s1, 0.f);
    const float bninv = 1.0f / sqrtf(1.0f + 1e-5f);
    h1[j] = gam[j] * (s1 * bninv) + bet[j];
    __syncthreads();
    if (j < 64) {
        float s2v = b2[j];
        for (int k = 0; k < AA; k++) s2v = fmaf(h1[k], w2[k*64 + j], s2v);
        h2[j] = fmaxf(s2v, 0.f);
    }
    __syncthreads();

    if (j == 0) {
        float lg[3];
        for (int c = 0; c < 3; c++) {
            float s = b3[c];
            for (int k = 0; k < 64; k++) s = fmaf(h2[k], w3[k*3 + c], s);
            lg[c] = s;
        }
        float m = fmaxf(lg[0], fmaxf(lg[1], lg[2]));
        float e0 = expf(lg[0]-m), e1 = expf(lg[1]-m), e2 = expf(lg[2]-m);
        float severity = e2 / (e0 + e1 + e2);

        float lam = (float)(num / den);
        float sync_ind = lam / (float)AA;
        float avg_corr = (float)(g_s.sum_rowsum / 16256.0);
        float sync_risk = fminf(1.0f, sync_ind * avg_corr);

        float cs0 = g_csstd[0], csl = g_csstd[TT-1];
        float avg_disp = (float)(g_s.sum_cs / (double)TT);
        float trend = (cs0 - csl) / (float)(TT - 1);
        float hi = fminf(fmaxf(trend / (avg_disp + 1e-6f) + 0.5f, 0.f), 1.f);

        float pl = (float)(g_s.cnt20 / (double)(TT - 20));

        float meanabs = (float)(g_s.sum_rowabs / ((double)AA * (double)AA));
        float retdiv = 1.0f - meanabs;
        float posdiv = 1.0f - pmax / (float)psum;
        float divloss = 1.0f - sqrtf(retdiv * posdiv);

        float hist = (float)((g_s.sum_r10 - g_s.sum_last5) / (double)(TT - 10 - 5));
        float rec  = (float)(g_s.sum_last5 / 5.0);
        float raw  = fminf(fmaxf((rec - hist) / hist, 0.f), 1.f);
        float surge = (hist > 0.f) ? raw : 0.f;

        float avgc = (float)((g_s.sum_conc / (double)TT - (double)AA) / 16256.0);
        float pc = fminf(fmaxf((avgc - 0.5f) * 2.0f, 0.f), 1.f);

        float coll = (hi + sync_risk + divloss) / 3.0f;

        out[0] = hi;      out[1] = severity; out[2] = sync_risk; out[3] = pl;
        out[4] = divloss; out[5] = surge;    out[6] = pc;        out[7] = coll;
    }
}

// ---------------- launch ----------------
extern "C" void kernel_launch(void* const* d_in, const int* in_sizes, int n_in,
                              void* d_out, int out_size) {
    const float* x    = (const float*)d_in[0];
    const float* pos  = (const float*)d_in[1];
    const float* w1   = (const float*)d_in[2];
    const float* b1   = (const float*)d_in[3];
    const float* gam  = (const float*)d_in[4];
    const float* bet  = (const float*)d_in[5];
    const float* w2   = (const float*)d_in[6];
    const float* b2   = (const float*)d_in[7];
    const float* w3   = (const float*)d_in[8];
    const float* b3   = (const float*)d_in[9];
    float* out = (float*)d_out;

    rowstats_kernel<<<256, 256>>>(x);
    covpart_kernel<<<NBCOV, 256>>>(x);
    covreduce_kernel<<<65, 256>>>();
    corr_kernel<<<128, 128>>>();

    int cur = 0;
    for (int k = 0; k < 12; k++) {
        int o = k & 1;
        square_kernel<<<16, 128>>>((k == 0) ? 1 : 0, cur, o);
        cur = o;
    }
    // cur == 1 after 12 steps

    rolling_kernel<20, TT-20><<<128, 256>>>(x);
    rolling_kernel<10, TT-10><<<128, 256>>>(x);

    scalars_kernel<<<1, 256>>>();
    final_kernel<<<1, 128>>>(x, pos, w1, b1, gam, bet, w2, b2, w3, b3, out, cur);
}

// round 7
// speedup vs baseline: 1.3937x; 1.3937x over previous
#include <cuda_runtime.h>
#include <math.h>

#define TT 8192
#define AA 128
#define NB 128      // grid size (one persistent wave, < 148 SMs)
#define NSQ 12      // squaring steps -> effective power 4096
#define NBG 33      // eigen-chain group: blocks 0..31 compute, block 32 does scalars

// ---------------- global scratch (static; no allocation) ----------------
__device__ float g_covpart[NB][AA*AA];   // 8.4 MB (L2-resident)
__device__ float g_colpart[NB][AA];
__device__ float g_corr[AA*AA];
__device__ float g_eig0[AA*AA];
__device__ float g_eig1[AA*AA];
__device__ float g_rowsum[AA];
__device__ float g_rowabs[AA];
__device__ float g_rowsq[AA];
__device__ float g_fp[2][32];
__device__ float g_roll20[TT];
__device__ float g_roll10[TT];
__device__ float g_csstd[TT];
__device__ float g_conc[TT];

struct ScalarsT {
    double sum_cs, sum_conc, sum_r10, sum_last5, sum_rowsum, sum_rowabs, cnt20;
};
__device__ ScalarsT g_s;

// sense-reversal barriers: [0] = full grid (128), [1] = eigen group (33)
__device__ unsigned g_bcnt[2];
__device__ unsigned g_bgen[2];

// ---------------- helpers ----------------
__device__ __forceinline__ float warpReduceAdd(float v) {
    #pragma unroll
    for (int o = 16; o; o >>= 1) v += __shfl_xor_sync(0xffffffffu, v, o);
    return v;
}

__device__ __forceinline__ void barrier_sync(int id, unsigned nb) {
    __syncthreads();
    if (threadIdx.x == 0) {
        __threadfence();
        volatile unsigned* genp = (volatile unsigned*)&g_bgen[id];
        unsigned g = *genp;
        unsigned old = atomicAdd(&g_bcnt[id], 1u);
        if (old == nb - 1u) {
            g_bcnt[id] = 0u;
            __threadfence();
            *genp = g + 1u;
        } else {
            while (*genp == g) __nanosleep(32);
        }
        __threadfence();
    }
    __syncthreads();
}

__device__ __forceinline__ double blockReduceAddD(double v, double* sh) {
    int tid = threadIdx.x;
    sh[tid] = v; __syncthreads();
    for (int s = 128; s; s >>= 1) {
        if (tid < s) sh[tid] += sh[tid + s];
        __syncthreads();
    }
    double r = sh[0]; __syncthreads();
    return r;
}

// ---------------- rolling off-diag corr via C.sum = sum_t (sum_a z_a)^2 ----------------
template<int W, int NWIN>
__device__ void roll_win(const float* sh, int base, int lane, int wid, float* out) {
    for (int q = 0; q < 8; q++) {
        int lw = wid * 8 + q;              // warp-uniform
        int widx = base + lw;
        if (widx >= NWIN) break;
        float S0=0,S1=0,S2=0,S3=0,Q0=0,Q1=0,Q2=0,Q3=0;
        #pragma unroll 5
        for (int t = 0; t < W; t++) {
            const float* row = sh + (lw + t) * AA + lane;
            float v0 = row[0], v1 = row[32], v2 = row[64], v3 = row[96];
            S0 += v0; Q0 = fmaf(v0, v0, Q0);
            S1 += v1; Q1 = fmaf(v1, v1, Q1);
            S2 += v2; Q2 = fmaf(v2, v2, Q2);
            S3 += v3; Q3 = fmaf(v3, v3, Q3);
        }
        const float iw = 1.0f / W;
        float i0 = rsqrtf(Q0 - S0*S0*iw);
        float i1 = rsqrtf(Q1 - S1*S1*iw);
        float i2 = rsqrtf(Q2 - S2*S2*iw);
        float i3 = rsqrtf(Q3 - S3*S3*iw);
        float part = S0*iw*i0 + S1*iw*i1 + S2*iw*i2 + S3*iw*i3;
        part = warpReduceAdd(part);        // sum_a mean_a * invd_a
        float acc = 0.f;
        #pragma unroll 5
        for (int t = 0; t < W; t++) {
            const float* row = sh + (lw + t) * AA + lane;
            float p = row[0]*i0 + row[32]*i1 + row[64]*i2 + row[96]*i3;
            p = warpReduceAdd(p);
            float s = p - part;            // sum_a z_a(t)
            acc = fmaf(s, s, acc);
        }
        if (lane == 0) out[widx] = (acc - (float)AA) * (1.0f/16256.0f);
    }
}

// ---------------- one squaring step: out = (in . in) / ||in||_F^2 ----------------
__device__ void square_step(int k, float* SM) {
    int tid = threadIdx.x;
    const float* in  = (k == 0) ? g_corr  : (((k-1) & 1) ? g_eig1 : g_eig0);
    float*       out = (k & 1) ? g_eig1 : g_eig0;
    const float* fpp = (k == 0) ? g_rowsq : g_fp[(k-1) & 1];
    int fpn = (k == 0) ? 128 : 32;
    float* shrow = SM;          // 512
    float* red   = SM + 512;    // 256

    red[tid] = (tid < fpn) ? fpp[tid] : 0.f;
    __syncthreads();
    for (int s = 128; s; s >>= 1) { if (tid < s) red[tid] += red[tid+s]; __syncthreads(); }
    float s2 = 1.0f / red[0];
    __syncthreads();

    int r0 = blockIdx.x * 4;
    shrow[tid]       = in[r0*AA + tid];
    shrow[tid + 256] = in[r0*AA + tid + 256];
    __syncthreads();

    int j = tid & 127, h = tid >> 7;
    const float* row0 = shrow + (2*h)*AA;
    const float* row1 = shrow + (2*h+1)*AA;
    float a0 = 0.f, a1 = 0.f;
    #pragma unroll 4
    for (int kk = 0; kk < AA; kk++) {
        float bk = in[kk*AA + j];
        a0 = fmaf(row0[kk], bk, a0);
        a1 = fmaf(row1[kk], bk, a1);
    }
    a0 *= s2; a1 *= s2;
    out[(r0 + 2*h)*AA + j]     = a0;
    out[(r0 + 2*h + 1)*AA + j] = a1;
    red[tid] = a0*a0 + a1*a1;
    __syncthreads();
    for (int s = 128; s; s >>= 1) { if (tid < s) red[tid] += red[tid+s]; __syncthreads(); }
    if (tid == 0) g_fp[k & 1][blockIdx.x] = red[0];
    __syncthreads();
}

// ---------------- fp64 scalar reductions (block 32) ----------------
__device__ void scalars_work(float* SM) {
    double* sd = (double*)SM;   // 256 doubles = 2048 B
    int tid = threadIdx.x;
    double a;
    a = 0; for (int i = tid; i < TT; i += 256) a += (double)g_csstd[i];
    double sum_cs = blockReduceAddD(a, sd);
    a = 0; for (int i = tid; i < TT; i += 256) a += (double)g_conc[i];
    double sum_conc = blockReduceAddD(a, sd);
    a = 0; for (int i = tid; i < TT-20; i += 256) a += (g_roll20[i] > 0.7f) ? 1.0 : 0.0;
    double cnt20 = blockReduceAddD(a, sd);
    a = 0; for (int i = tid; i < TT-10; i += 256) a += (double)g_roll10[i];
    double sum_r10 = blockReduceAddD(a, sd);
    a = (tid < AA) ? (double)g_rowsum[tid] : 0.0;
    double sum_rowsum = blockReduceAddD(a, sd);
    a = (tid < AA) ? (double)g_rowabs[tid] : 0.0;
    double sum_rowabs = blockReduceAddD(a, sd);
    if (tid == 0) {
        double l5 = 0;
        for (int i = TT - 15; i < TT - 10; i++) l5 += (double)g_roll10[i];
        g_s.sum_cs = sum_cs; g_s.sum_conc = sum_conc; g_s.cnt20 = cnt20;
        g_s.sum_r10 = sum_r10; g_s.sum_last5 = l5;
        g_s.sum_rowsum = sum_rowsum; g_s.sum_rowabs = sum_rowabs;
    }
}

// ---------------- Rayleigh quotient + MLP + assembly (block 0) ----------------
__device__ void final_work(const float* x, const float* pos,
        const float* w1, const float* b1, const float* gam, const float* bet,
        const float* w2, const float* b2, const float* w3, const float* b3,
        float* out, float* SM) {
    int tid = threadIdx.x;
    float* feats = SM;                    // 256
    float* h1    = SM + 256;              // 128
    float* h2    = SM + 384;              // 64
    float* vvec  = SM + 448;              // 128
    float* rf    = SM + 576;              // 128
    int*   ri    = (int*)(SM + 704);      // 128
    double* rd   = (double*)(SM + 832);   // 128 doubles (byte off 3328, 8-aligned)
    const float* Bf = g_eig1;             // NSQ=12 -> last out buffer

    if (tid < 128) {
        feats[tid]       = x[(size_t)(TT-1)*AA + tid];
        feats[128 + tid] = pos[tid];
        rf[tid] = Bf[tid*AA + tid];
        ri[tid] = tid;
    }
    __syncthreads();
    for (int s = 64; s; s >>= 1) {
        if (tid < s && rf[tid+s] > rf[tid]) { rf[tid] = rf[tid+s]; ri[tid] = ri[tid+s]; }
        __syncthreads();
    }
    int jstar = ri[0];
    __syncthreads();
    if (tid < 128) vvec[tid] = Bf[jstar*AA + tid];
    __syncthreads();

    if (tid < 128) {
        float y = 0.f;
        #pragma unroll 4
        for (int k = 0; k < AA; k++) y = fmaf(g_corr[tid*AA + k], vvec[k], y);
        rd[tid] = (double)vvec[tid] * (double)y;
    }
    __syncthreads();
    for (int s = 64; s; s >>= 1) { if (tid < s) rd[tid] += rd[tid+s]; __syncthreads(); }
    double num = rd[0]; __syncthreads();
    if (tid < 128) rd[tid] = (double)vvec[tid] * (double)vvec[tid];
    __syncthreads();
    for (int s = 64; s; s >>= 1) { if (tid < s) rd[tid] += rd[tid+s]; __syncthreads(); }
    double den = rd[0]; __syncthreads();

    float pa = (tid < 128) ? fabsf(pos[tid]) : 0.f;
    if (tid < 128) rd[tid] = (double)pa;
    __syncthreads();
    for (int s = 64; s; s >>= 1) { if (tid < s) rd[tid] += rd[tid+s]; __syncthreads(); }
    double psum = rd[0]; __syncthreads();
    if (tid < 128) rf[tid] = pa;
    __syncthreads();
    for (int s = 64; s; s >>= 1) { if (tid < s) rf[tid] = fmaxf(rf[tid], rf[tid+s]); __syncthreads(); }
    float pmax = rf[0]; __syncthreads();

    // MLP
    if (tid < 128) {
        float s1 = b1[tid];
        #pragma unroll 4
        for (int k = 0; k < 2*AA; k++) s1 = fmaf(feats[k], w1[k*AA + tid], s1);
        s1 = fmaxf(s1, 0.f);
        const float bninv = 1.0f / sqrtf(1.0f + 1e-5f);
        h1[tid] = gam[tid] * (s1 * bninv) + bet[tid];
    }
    __syncthreads();
    if (tid < 64) {
        float s2v = b2[tid];
        #pragma unroll 4
        for (int k = 0; k < AA; k++) s2v = fmaf(h1[k], w2[k*64 + tid], s2v);
        h2[tid] = fmaxf(s2v, 0.f);
    }
    __syncthreads();

    if (tid == 0) {
        float lg[3];
        for (int c = 0; c < 3; c++) {
            float s = b3[c];
            for (int k = 0; k < 64; k++) s = fmaf(h2[k], w3[k*3 + c], s);
            lg[c] = s;
        }
        float m = fmaxf(lg[0], fmaxf(lg[1], lg[2]));
        float e0 = expf(lg[0]-m), e1 = expf(lg[1]-m), e2 = expf(lg[2]-m);
        float severity = e2 / (e0 + e1 + e2);

        float lam = (float)(num / den);
        float sync_ind = lam / (float)AA;
        float avg_corr = (float)(g_s.sum_rowsum / 16256.0);
        float sync_risk = fminf(1.0f, sync_ind * avg_corr);

        float cs0 = g_csstd[0], csl = g_csstd[TT-1];
        float avg_disp = (float)(g_s.sum_cs / (double)TT);
        float trend = (cs0 - csl) / (float)(TT - 1);
        float hi = fminf(fmaxf(trend / (avg_disp + 1e-6f) + 0.5f, 0.f), 1.f);

        float pl = (float)(g_s.cnt20 / (double)(TT - 20));

        float meanabs = (float)(g_s.sum_rowabs / ((double)AA * (double)AA));
        float retdiv = 1.0f - meanabs;
        float posdiv = 1.0f - pmax / (float)psum;
        float divloss = 1.0f - sqrtf(retdiv * posdiv);

        float hist = (float)((g_s.sum_r10 - g_s.sum_last5) / (double)(TT - 10 - 5));
        float rec  = (float)(g_s.sum_last5 / 5.0);
        float raw  = fminf(fmaxf((rec - hist) / hist, 0.f), 1.f);
        float surge = (hist > 0.f) ? raw : 0.f;

        float avgc = (float)((g_s.sum_conc / (double)TT - (double)AA) / 16256.0);
        float pc = fminf(fmaxf((avgc - 0.5f) * 2.0f, 0.f), 1.f);

        float coll = (hi + sync_risk + divloss) / 3.0f;

        out[0] = hi;      out[1] = severity; out[2] = sync_risk; out[3] = pl;
        out[4] = divloss; out[5] = surge;    out[6] = pc;        out[7] = coll;
    }
}

// ---------------- the single fused kernel ----------------
__global__ void __launch_bounds__(256)
fused_kernel(const float* __restrict__ x, const float* __restrict__ pos,
             const float* __restrict__ w1, const float* __restrict__ b1,
             const float* __restrict__ gam, const float* __restrict__ bet,
             const float* __restrict__ w2, const float* __restrict__ b2,
             const float* __restrict__ w3, const float* __restrict__ b3,
             float* __restrict__ out) {
    __shared__ __align__(16) float SM[10624];   // 42.5 KB, re-carved per phase
    int tid = threadIdx.x;
    int b = blockIdx.x;
    int wid = tid >> 5, lane = tid & 31;

    // ================= Phase A: tile (83 rows), Gram partials, row stats, rolling =================
    {
        float* tile = SM;
        int base = b * 64;
        for (int idx = tid; idx < 83 * AA; idx += 256) {
            int r = idx >> 7, c = idx & 127;
            int gr = base + r;
            tile[idx] = (gr < TT) ? x[(size_t)gr * AA + c] : 0.f;
        }
        __syncthreads();

        // Gram partial: 16x16 threads, 8x8 micro-tiles over first 64 rows
        {
            int ti = tid >> 4, tj = tid & 15;
            int i0 = ti * 8, j0 = tj * 8;
            float acc[8][8] = {};
            for (int t = 0; t < 64; t++) {
                float a[8], bb[8];
                *reinterpret_cast<float4*>(a)      = *reinterpret_cast<float4*>(&tile[t*AA + i0]);
                *reinterpret_cast<float4*>(a + 4)  = *reinterpret_cast<float4*>(&tile[t*AA + i0 + 4]);
                *reinterpret_cast<float4*>(bb)     = *reinterpret_cast<float4*>(&tile[t*AA + j0]);
                *reinterpret_cast<float4*>(bb + 4) = *reinterpret_cast<float4*>(&tile[t*AA + j0 + 4]);
                #pragma unroll
                for (int ii = 0; ii < 8; ii++)
                    #pragma unroll
                    for (int jj = 0; jj < 8; jj++)
                        acc[ii][jj] = fmaf(a[ii], bb[jj], acc[ii][jj]);
            }
            float* outp = g_covpart[b];
            #pragma unroll
            for (int ii = 0; ii < 8; ii++)
                #pragma unroll
                for (int jj = 0; jj < 8; jj++)
                    outp[(i0+ii)*AA + (j0+jj)] = acc[ii][jj];
        }

        // column sums of first 64 rows
        if (tid < AA) {
            float cs = 0.f;
            for (int t = 0; t < 64; t++) cs += tile[t*AA + tid];
            g_colpart[b][tid] = cs;
        }

        // per-row stats: csstd (ddof=1) + sign concordance; 8 warps x 8 rows
        for (int q = 0; q < 8; q++) {
            int lr = wid * 8 + q;
            int r = base + lr;
            float4 v = reinterpret_cast<float4*>(tile)[lr*32 + lane];
            float s = v.x + v.y + v.z + v.w;
            float qq = v.x*v.x + v.y*v.y + v.z*v.z + v.w*v.w;
            float p = ((v.x>0.f)?1.f:0.f)+((v.y>0.f)?1.f:0.f)+((v.z>0.f)?1.f:0.f)+((v.w>0.f)?1.f:0.f);
            float n = ((v.x<0.f)?1.f:0.f)+((v.y<0.f)?1.f:0.f)+((v.z<0.f)?1.f:0.f)+((v.w<0.f)?1.f:0.f);
            s = warpReduceAdd(s); qq = warpReduceAdd(qq);
            p = warpReduceAdd(p); n = warpReduceAdd(n);
            if (lane == 0) {
                float var = (qq - s*s*(1.0f/AA)) * (1.0f/(AA-1));
                g_csstd[r] = sqrtf(fmaxf(var, 0.f));
                float z = (float)AA - p - n;
                g_conc[r] = p*p + n*n + z*z;
            }
        }

        // rolling windows (both W from same tile)
        roll_win<20, TT-20>(tile, base, lane, wid, g_roll20);
        roll_win<10, TT-10>(tile, base, lane, wid, g_roll10);
    }

    barrier_sync(0, NB);

    // ================= Phase B: corr row i = blockIdx.x, + row partials =================
    {
        float* colv = SM;         // 128
        float* invd = SM + 128;   // 128
        float* red  = SM + 256;   // 256
        if (tid < AA) {
            float s = 0.f;
            #pragma unroll 4
            for (int bb = 0; bb < NB; bb++) s += g_colpart[bb][tid];
            colv[tid] = s;
            float d = 0.f;
            #pragma unroll 4
            for (int bb = 0; bb < NB; bb++) d += g_covpart[bb][tid*AA + tid];
            invd[tid] = rsqrtf(d - s * s * (1.0f/TT));
        }
        __syncthreads();

        int i = b;
        int j = tid & 127, h = tid >> 7;
        float s = 0.f;
        #pragma unroll 4
        for (int bb = h*64; bb < h*64 + 64; bb++) s += g_covpart[bb][i*AA + j];
        red[tid] = s;
        __syncthreads();
        float c = 0.f;
        if (tid < 128) {
            float covij = red[j] + red[128 + j];
            c = (covij - colv[i] * colv[j] * (1.0f/TT)) * invd[i] * invd[j];
            g_corr[i*AA + j] = c;
        }
        __syncthreads();

        // row partials via warp shuffles (4 active warps when tid<128)
        float coff = (tid < 128) ? ((j == i) ? 0.f : c) : 0.f;
        float cab  = (tid < 128) ? fabsf(c) : 0.f;
        float csq  = (tid < 128) ? c*c : 0.f;
        coff = warpReduceAdd(coff);
        cab  = warpReduceAdd(cab);
        csq  = warpReduceAdd(csq);
        if (lane == 0) {
            red[wid]      = coff;
            red[8 + wid]  = cab;
            red[16 + wid] = csq;
        }
        __syncthreads();
        if (tid == 0) {
            g_rowsum[i] = red[0] + red[1] + red[2] + red[3];
            g_rowabs[i] = red[8] + red[9] + red[10] + red[11];
            g_rowsq[i]  = red[16] + red[17] + red[18] + red[19];
        }
    }

    barrier_sync(0, NB);

    // ================= Phase C: eigen chain (blocks 0..31) + scalars (block 32) =================
    if (b < NBG) {
        for (int k = 0; k < NSQ; k++) {
            if (b < 32) square_step(k, SM);
            else if (k == 0) scalars_work(SM);
            barrier_sync(1, NBG);
        }
        if (b == 0) {
            final_work(x, pos, w1, b1, gam, bet, w2, b2, w3, b3, out, SM);
        }
    }
}

// ---------------- launch ----------------
extern "C" void kernel_launch(void* const* d_in, const int* in_sizes, int n_in,
                              void* d_out, int out_size) {
    const float* x    = (const float*)d_in[0];
    const float* pos  = (const float*)d_in[1];
    const float* w1   = (const float*)d_in[2];
    const float* b1   = (const float*)d_in[3];
    const float* gam  = (const float*)d_in[4];
    const float* bet  = (const float*)d_in[5];
    const float* w2   = (const float*)d_in[6];
    const float* b2   = (const float*)d_in[7];
    const float* w3   = (const float*)d_in[8];
    const float* b3   = (const float*)d_in[9];
    float* out = (float*)d_out;

    fused_kernel<<<NB, 256>>>(x, pos, w1, b1, gam, bet, w2, b2, w3, b3, out);
}

// round 10
// speedup vs baseline: 1.8208x; 1.3064x over previous
#include <cuda_runtime.h>
#include <math.h>

#define TT 8192
#define AA 128
#define NB 128      // grid: one co-resident wave (< 148 SMs)
#define NT 512      // threads per block (16 warps, occ 25%)
#define NSQ 10      // squaring steps -> effective power 1024
#define NCH 16      // chain blocks (8 rows each)
#define NBG 17      // chain group: 16 compute + 1 scalars

// ---------------- global scratch (static; no allocation) ----------------
__device__ float g_covpart[NB][AA*AA];   // 8.4 MB (L2-resident)
__device__ float g_colpart[NB][AA];
__device__ float g_corr[AA*AA];
__device__ float g_eig0[AA*AA];
__device__ float g_eig1[AA*AA];
__device__ float g_rowsum[AA];
__device__ float g_rowabs[AA];
__device__ float g_rowsq[AA];
__device__ float g_fp[2][NCH];
__device__ float g_roll20[TT];
__device__ float g_roll10[TT];
__device__ float g_csstd[TT];
__device__ float g_conc[TT];

struct ScalarsT {
    double sum_cs, sum_conc, sum_r10, sum_last5, sum_rowsum, sum_rowabs, cnt20;
};
__device__ ScalarsT g_s;

// sense-reversal barriers: [0] = full grid (128), [1] = chain group (17)
__device__ unsigned g_bcnt[2];
__device__ unsigned g_bgen[2];

// ---------------- helpers ----------------
__device__ __forceinline__ float warpReduceAdd(float v) {
    #pragma unroll
    for (int o = 16; o; o >>= 1) v += __shfl_xor_sync(0xffffffffu, v, o);
    return v;
}

__device__ __forceinline__ void barrier_sync(int id, unsigned nb) {
    __syncthreads();
    if (threadIdx.x == 0) {
        __threadfence();
        volatile unsigned* genp = (volatile unsigned*)&g_bgen[id];
        unsigned g = *genp;
        unsigned old = atomicAdd(&g_bcnt[id], 1u);
        if (old == nb - 1u) {
            g_bcnt[id] = 0u;
            __threadfence();
            *genp = g + 1u;
        } else {
            while (*genp == g) __nanosleep(32);
        }
        __threadfence();
    }
    __syncthreads();
}

__device__ __forceinline__ double blockReduceAddD(double v, double* sh) {
    int tid = threadIdx.x;
    sh[tid] = v; __syncthreads();
    for (int s = NT/2; s; s >>= 1) {
        if (tid < s) sh[tid] += sh[tid + s];
        __syncthreads();
    }
    double r = sh[0]; __syncthreads();
    return r;
}

// ---------------- rolling off-diag corr via C.sum = sum_t (sum_a z_a)^2 ----------------
// 16 warps x 4 windows each
template<int W, int NWIN>
__device__ void roll_win(const float* sh, int base, int lane, int wid, float* out) {
    for (int q = 0; q < 4; q++) {
        int lw = wid * 4 + q;              // warp-uniform
        int widx = base + lw;
        if (widx >= NWIN) break;
        float S0=0,S1=0,S2=0,S3=0,Q0=0,Q1=0,Q2=0,Q3=0;
        #pragma unroll 5
        for (int t = 0; t < W; t++) {
            const float* row = sh + (lw + t) * AA + lane;
            float v0 = row[0], v1 = row[32], v2 = row[64], v3 = row[96];
            S0 += v0; Q0 = fmaf(v0, v0, Q0);
            S1 += v1; Q1 = fmaf(v1, v1, Q1);
            S2 += v2; Q2 = fmaf(v2, v2, Q2);
            S3 += v3; Q3 = fmaf(v3, v3, Q3);
        }
        const float iw = 1.0f / W;
        float i0 = rsqrtf(Q0 - S0*S0*iw);
        float i1 = rsqrtf(Q1 - S1*S1*iw);
        float i2 = rsqrtf(Q2 - S2*S2*iw);
        float i3 = rsqrtf(Q3 - S3*S3*iw);
        float part = S0*iw*i0 + S1*iw*i1 + S2*iw*i2 + S3*iw*i3;
        part = warpReduceAdd(part);        // sum_a mean_a * invd_a
        float acc = 0.f;
        #pragma unroll 5
        for (int t = 0; t < W; t++) {
            const float* row = sh + (lw + t) * AA + lane;
            float p = row[0]*i0 + row[32]*i1 + row[64]*i2 + row[96]*i3;
            p = warpReduceAdd(p);
            float s = p - part;            // sum_a z_a(t)
            acc = fmaf(s, s, acc);
        }
        if (lane == 0) out[widx] = (acc - (float)AA) * (1.0f/16256.0f);
    }
}

// ---------------- one squaring step: out = (in . in) / ||in||_F^2 ----------------
// 16 blocks x 8 rows, 512 threads; B staged through smem in 32-row chunks
__device__ void square_step(int k, float* SM) {
    int tid = threadIdx.x;
    const float* in  = (k == 0) ? g_corr  : (((k-1) & 1) ? g_eig1 : g_eig0);
    float*       out = (k & 1) ? g_eig1 : g_eig0;
    const float* fpp = (k == 0) ? g_rowsq : g_fp[(k-1) & 1];
    int fpn = (k == 0) ? 128 : NCH;
    float* shrow = SM;          // 1024 floats: 8 rows of A-side
    float* bsh   = SM + 1024;   // 4096 floats: 32-row chunk of B-side
    float* red   = SM + 5120;   // 128 floats scratch

    // Frobenius sum (single warp)
    if (tid < 32) {
        float v = (tid < fpn) ? fpp[tid] : 0.f;
        if (fpn == 128) v += fpp[tid+32] + fpp[tid+64] + fpp[tid+96];
        v = warpReduceAdd(v);
        if (tid == 0) red[0] = v;
    }
    int r0 = blockIdx.x * 8;
    shrow[tid]       = in[r0*AA + tid];
    shrow[tid + 512] = in[r0*AA + tid + 512];
    __syncthreads();
    float s2 = 1.0f / red[0];

    int j = tid & 127, h = tid >> 7;   // h in 0..3 -> rows 2h, 2h+1
    float a0 = 0.f, a1 = 0.f;
    #pragma unroll
    for (int c = 0; c < 4; c++) {
        // stage rows c*32 .. c*32+31 of in (coalesced float4)
        reinterpret_cast<float4*>(bsh)[tid]       = reinterpret_cast<const float4*>(in + c*32*AA)[tid];
        reinterpret_cast<float4*>(bsh)[tid + 512] = reinterpret_cast<const float4*>(in + c*32*AA)[tid + 512];
        __syncthreads();
        const float* r0p = shrow + (2*h)*AA + c*32;
        const float* r1p = shrow + (2*h+1)*AA + c*32;
        #pragma unroll 8
        for (int kk = 0; kk < 32; kk++) {
            float bk = bsh[kk*AA + j];     // conflict-free (consecutive j per warp)
            a0 = fmaf(r0p[kk], bk, a0);    // broadcast
            a1 = fmaf(r1p[kk], bk, a1);
        }
        __syncthreads();
    }
    a0 *= s2; a1 *= s2;
    out[(r0 + 2*h)*AA + j]     = a0;
    out[(r0 + 2*h + 1)*AA + j] = a1;

    float ps = warpReduceAdd(a0*a0 + a1*a1);
    if ((tid & 31) == 0) red[64 + (tid >> 5)] = ps;
    __syncthreads();
    if (tid == 0) {
        float s = 0.f;
        #pragma unroll
        for (int w = 0; w < 16; w++) s += red[64 + w];
        g_fp[k & 1][blockIdx.x] = s;
    }
}

// ---------------- fp64 scalar reductions (block 16, concurrent with chain) ----------------
__device__ void scalars_work(float* SM) {
    double* sd = (double*)SM;   // 512 doubles = 4 KB
    int tid = threadIdx.x;
    double a;
    a = 0; for (int i = tid; i < TT; i += NT) a += (double)g_csstd[i];
    double sum_cs = blockReduceAddD(a, sd);
    a = 0; for (int i = tid; i < TT; i += NT) a += (double)g_conc[i];
    double sum_conc = blockReduceAddD(a, sd);
    a = 0; for (int i = tid; i < TT-20; i += NT) a += (g_roll20[i] > 0.7f) ? 1.0 : 0.0;
    double cnt20 = blockReduceAddD(a, sd);
    a = 0; for (int i = tid; i < TT-10; i += NT) a += (double)g_roll10[i];
    double sum_r10 = blockReduceAddD(a, sd);
    a = (tid < AA) ? (double)g_rowsum[tid] : 0.0;
    double sum_rowsum = blockReduceAddD(a, sd);
    a = (tid < AA) ? (double)g_rowabs[tid] : 0.0;
    double sum_rowabs = blockReduceAddD(a, sd);
    if (tid == 0) {
        double l5 = 0;
        for (int i = TT - 15; i < TT - 10; i++) l5 += (double)g_roll10[i];
        g_s.sum_cs = sum_cs; g_s.sum_conc = sum_conc; g_s.cnt20 = cnt20;
        g_s.sum_r10 = sum_r10; g_s.sum_last5 = l5;
        g_s.sum_rowsum = sum_rowsum; g_s.sum_rowabs = sum_rowabs;
    }
}

// ---------------- Rayleigh quotient + MLP + assembly (block 0) ----------------
__device__ void final_work(const float* x, const float* pos,
        const float* w1, const float* b1, const float* gam, const float* bet,
        const float* w2, const float* b2, const float* w3, const float* b3,
        float* out, float* SM) {
    int tid = threadIdx.x;
    float* feats = SM;                    // 256
    float* h1    = SM + 256;              // 128
    float* h2    = SM + 384;              // 64
    float* vvec  = SM + 448;              // 128
    float* rf    = SM + 576;              // 128
    int*   ri    = (int*)(SM + 704);      // 128
    double* rd   = (double*)(SM + 832);   // 128 doubles (byte 3328, 8-aligned)
    const float* Bf = (NSQ & 1) ? g_eig1 : g_eig0;   // step NSQ-1 writes (NSQ-1)&1

    if (tid < 128) {
        feats[tid]       = x[(size_t)(TT-1)*AA + tid];
        feats[128 + tid] = pos[tid];
        rf[tid] = Bf[tid*AA + tid];
        ri[tid] = tid;
    }
    __syncthreads();
    for (int s = 64; s; s >>= 1) {
        if (tid < s && rf[tid+s] > rf[tid]) { rf[tid] = rf[tid+s]; ri[tid] = ri[tid+s]; }
        __syncthreads();
    }
    int jstar = ri[0];
    __syncthreads();
    if (tid < 128) vvec[tid] = Bf[jstar*AA + tid];   // row jstar = col jstar (symmetric)
    __syncthreads();

    if (tid < 128) {
        // y = C v using symmetry: read C row-k contiguous (coalesced)
        float y = 0.f;
        #pragma unroll 4
        for (int k = 0; k < AA; k++) y = fmaf(g_corr[k*AA + tid], vvec[k], y);
        rd[tid] = (double)vvec[tid] * (double)y;
    }
    __syncthreads();
    for (int s = 64; s; s >>= 1) { if (tid < s) rd[tid] += rd[tid+s]; __syncthreads(); }
    double num = rd[0]; __syncthreads();
    if (tid < 128) rd[tid] = (double)vvec[tid] * (double)vvec[tid];
    __syncthreads();
    for (int s = 64; s; s >>= 1) { if (tid < s) rd[tid] += rd[tid+s]; __syncthreads(); }
    double den = rd[0]; __syncthreads();

    float pa = (tid < 128) ? fabsf(pos[tid]) : 0.f;
    if (tid < 128) rd[tid] = (double)pa;
    __syncthreads();
    for (int s = 64; s; s >>= 1) { if (tid < s) rd[tid] += rd[tid+s]; __syncthreads(); }
    double psum = rd[0]; __syncthreads();
    if (tid < 128) rf[tid] = pa;
    __syncthreads();
    for (int s = 64; s; s >>= 1) { if (tid < s) rf[tid] = fmaxf(rf[tid], rf[tid+s]); __syncthreads(); }
    float pmax = rf[0]; __syncthreads();

    // MLP
    if (tid < 128) {
        float s1 = b1[tid];
        #pragma unroll 4
        for (int k = 0; k < 2*AA; k++) s1 = fmaf(feats[k], w1[k*AA + tid], s1);
        s1 = fmaxf(s1, 0.f);
        const float bninv = 1.0f / sqrtf(1.0f + 1e-5f);
        h1[tid] = gam[tid] * (s1 * bninv) + bet[tid];
    }
    __syncthreads();
    if (tid < 64) {
        float s2v = b2[tid];
        #pragma unroll 4
        for (int k = 0; k < AA; k++) s2v = fmaf(h1[k], w2[k*64 + tid], s2v);
        h2[tid] = fmaxf(s2v, 0.f);
    }
    __syncthreads();

    if (tid == 0) {
        float lg[3];
        for (int c = 0; c < 3; c++) {
            float s = b3[c];
            for (int k = 0; k < 64; k++) s = fmaf(h2[k], w3[k*3 + c], s);
            lg[c] = s;
        }
        float m = fmaxf(lg[0], fmaxf(lg[1], lg[2]));
        float e0 = expf(lg[0]-m), e1 = expf(lg[1]-m), e2 = expf(lg[2]-m);
        float severity = e2 / (e0 + e1 + e2);

        float lam = (float)(num / den);
        float sync_ind = lam / (float)AA;
        float avg_corr = (float)(g_s.sum_rowsum / 16256.0);
        float sync_risk = fminf(1.0f, sync_ind * avg_corr);

        float cs0 = g_csstd[0], csl = g_csstd[TT-1];
        float avg_disp = (float)(g_s.sum_cs / (double)TT);
        float trend = (cs0 - csl) / (float)(TT - 1);
        float hi = fminf(fmaxf(trend / (avg_disp + 1e-6f) + 0.5f, 0.f), 1.f);

        float pl = (float)(g_s.cnt20 / (double)(TT - 20));

        float meanabs = (float)(g_s.sum_rowabs / ((double)AA * (double)AA));
        float retdiv = 1.0f - meanabs;
        float posdiv = 1.0f - pmax / (float)psum;
        float divloss = 1.0f - sqrtf(retdiv * posdiv);

        float hist = (float)((g_s.sum_r10 - g_s.sum_last5) / (double)(TT - 10 - 5));
        float rec  = (float)(g_s.sum_last5 / 5.0);
        float raw  = fminf(fmaxf((rec - hist) / hist, 0.f), 1.f);
        float surge = (hist > 0.f) ? raw : 0.f;

        float avgc = (float)((g_s.sum_conc / (double)TT - (double)AA) / 16256.0);
        float pc = fminf(fmaxf((avgc - 0.5f) * 2.0f, 0.f), 1.f);

        float coll = (hi + sync_risk + divloss) / 3.0f;

        out[0] = hi;      out[1] = severity; out[2] = sync_risk; out[3] = pl;
        out[4] = divloss; out[5] = surge;    out[6] = pc;        out[7] = coll;
    }
}

// ---------------- the single fused kernel ----------------
__global__ void __launch_bounds__(NT, 1)
fused_kernel(const float* __restrict__ x, const float* __restrict__ pos,
             const float* __restrict__ w1, const float* __restrict__ b1,
             const float* __restrict__ gam, const float* __restrict__ bet,
             const float* __restrict__ w2, const float* __restrict__ b2,
             const float* __restrict__ w3, const float* __restrict__ b3,
             float* __restrict__ out) {
    __shared__ __align__(16) float SM[10624];   // 42.5 KB, re-carved per phase
    int tid = threadIdx.x;
    int b = blockIdx.x;
    int wid = tid >> 5, lane = tid & 31;

    // ================= Phase A: tile (83 rows), Gram partial, row stats, rolling =================
    {
        float* tile = SM;
        int base = b * 64;
        const float4* xv = reinterpret_cast<const float4*>(x);
        float4* tv = reinterpret_cast<float4*>(tile);
        #pragma unroll
        for (int it = 0; it < 6; it++) {
            int idx = tid + it * NT;               // float4 index within tile
            if (idx < 83 * 32) {
                int gr = base + (idx >> 5);
                tv[idx] = (gr < TT) ? xv[(size_t)base * 32 + idx]
                                    : make_float4(0.f, 0.f, 0.f, 0.f);
            }
        }
        __syncthreads();

        // Gram partial over first 64 rows: 32x16 thread grid, 4x8 micro-tiles
        {
            int ti = tid >> 4, tj = tid & 15;
            int i0 = ti * 4, j0 = tj * 8;
            float acc[4][8] = {};
            for (int t = 0; t < 64; t++) {
                float a[4], bb8[8];
                *reinterpret_cast<float4*>(a)       = *reinterpret_cast<float4*>(&tile[t*AA + i0]);
                *reinterpret_cast<float4*>(bb8)     = *reinterpret_cast<float4*>(&tile[t*AA + j0]);
                *reinterpret_cast<float4*>(bb8 + 4) = *reinterpret_cast<float4*>(&tile[t*AA + j0 + 4]);
                #pragma unroll
                for (int ii = 0; ii < 4; ii++)
                    #pragma unroll
                    for (int jj = 0; jj < 8; jj++)
                        acc[ii][jj] = fmaf(a[ii], bb8[jj], acc[ii][jj]);
            }
            float* outp = g_covpart[b];
            #pragma unroll
            for (int ii = 0; ii < 4; ii++)
                #pragma unroll
                for (int jj = 0; jj < 8; jj++)
                    outp[(i0+ii)*AA + (j0+jj)] = acc[ii][jj];
        }

        // column sums of first 64 rows
        if (tid < AA) {
            float cs = 0.f;
            #pragma unroll 4
            for (int t = 0; t < 64; t++) cs += tile[t*AA + tid];
            g_colpart[b][tid] = cs;
        }

        // per-row stats: csstd (ddof=1) + sign concordance; 16 warps x 4 rows
        #pragma unroll
        for (int q = 0; q < 4; q++) {
            int lr = wid * 4 + q;
            int r = base + lr;
            float4 v = reinterpret_cast<float4*>(tile)[lr*32 + lane];
            float s = v.x + v.y + v.z + v.w;
            float qq = v.x*v.x + v.y*v.y + v.z*v.z + v.w*v.w;
            float p = ((v.x>0.f)?1.f:0.f)+((v.y>0.f)?1.f:0.f)+((v.z>0.f)?1.f:0.f)+((v.w>0.f)?1.f:0.f);
            float n = ((v.x<0.f)?1.f:0.f)+((v.y<0.f)?1.f:0.f)+((v.z<0.f)?1.f:0.f)+((v.w<0.f)?1.f:0.f);
            s = warpReduceAdd(s); qq = warpReduceAdd(qq);
            p = warpReduceAdd(p); n = warpReduceAdd(n);
            if (lane == 0) {
                float var = (qq - s*s*(1.0f/AA)) * (1.0f/(AA-1));
                g_csstd[r] = sqrtf(fmaxf(var, 0.f));
                float z = (float)AA - p - n;
                g_conc[r] = p*p + n*n + z*z;
            }
        }

        // rolling windows (both W from same tile)
        roll_win<20, TT-20>(tile, base, lane, wid, g_roll20);
        roll_win<10, TT-10>(tile, base, lane, wid, g_roll10);
    }

    barrier_sync(0, NB);

    // ================= Phase B: corr row i = blockIdx.x, + row partials =================
    {
        float* colv = SM;           // 128
        float* invd = SM + 128;     // 128
        float* redA = SM + 256;     // 512
        float* redB = SM + 768;     // 512
        int jj = tid & 127, hh = tid >> 7;
        {
            float s = 0.f, d = 0.f;
            #pragma unroll 4
            for (int bb = hh*32; bb < hh*32 + 32; bb++) {
                s += g_colpart[bb][jj];
                d += g_covpart[bb][jj*AA + jj];
            }
            redA[hh*128 + jj] = s;
            redB[hh*128 + jj] = d;
        }
        __syncthreads();
        if (tid < 128) {
            float s = redA[tid] + redA[128+tid] + redA[256+tid] + redA[384+tid];
            float d = redB[tid] + redB[128+tid] + redB[256+tid] + redB[384+tid];
            colv[tid] = s;
            invd[tid] = rsqrtf(d - s * s * (1.0f/TT));
        }
        __syncthreads();

        int i = b;
        float s = 0.f;
        #pragma unroll 4
        for (int bb = hh*32; bb < hh*32 + 32; bb++) s += g_covpart[bb][i*AA + jj];
        redA[hh*128 + jj] = s;
        __syncthreads();
        float c = 0.f;
        if (tid < 128) {
            float covij = redA[jj] + redA[128+jj] + redA[256+jj] + redA[384+jj];
            c = (covij - colv[i] * colv[jj] * (1.0f/TT)) * invd[i] * invd[jj];
            g_corr[i*AA + jj] = c;
        }
        __syncthreads();   // before redB reuse

        float coff = (tid < 128) ? ((jj == i) ? 0.f : c) : 0.f;
        float cab  = (tid < 128) ? fabsf(c) : 0.f;
        float csq  = (tid < 128) ? c*c : 0.f;
        coff = warpReduceAdd(coff);
        cab  = warpReduceAdd(cab);
        csq  = warpReduceAdd(csq);
        if (lane == 0) {
            redB[wid]      = coff;
            redB[16 + wid] = cab;
            redB[32 + wid] = csq;
        }
        __syncthreads();
        if (tid == 0) {
            float s0 = 0.f, s1 = 0.f, s2 = 0.f;
            #pragma unroll
            for (int w = 0; w < 16; w++) { s0 += redB[w]; s1 += redB[16+w]; s2 += redB[32+w]; }
            g_rowsum[i] = s0; g_rowabs[i] = s1; g_rowsq[i] = s2;
        }
    }

    barrier_sync(0, NB);

    // ================= Phase C: eigen chain (blocks 0..15) + scalars (block 16) =================
    if (b < NBG) {
        for (int k = 0; k < NSQ; k++) {
            if (b < NCH) square_step(k, SM);
            else if (k == 0) scalars_work(SM);
            barrier_sync(1, NBG);
        }
        if (b == 0) {
            final_work(x, pos, w1, b1, gam, bet, w2, b2, w3, b3, out, SM);
        }
    }
}

// ---------------- launch ----------------
extern "C" void kernel_launch(void* const* d_in, const int* in_sizes, int n_in,
                              void* d_out, int out_size) {
    const float* x    = (const float*)d_in[0];
    const float* pos  = (const float*)d_in[1];
    const float* w1   = (const float*)d_in[2];
    const float* b1   = (const float*)d_in[3];
    const float* gam  = (const float*)d_in[4];
    const float* bet  = (const float*)d_in[5];
    const float* w2   = (const float*)d_in[6];
    const float* b2   = (const float*)d_in[7];
    const float* w3   = (const float*)d_in[8];
    const float* b3   = (const float*)d_in[9];
    float* out = (float*)d_out;

    fused_kernel<<<NB, NT>>>(x, pos, w1, b1, gam, bet, w2, b2, w3, b3, out);
}

// round 14
// speedup vs baseline: 3.0456x; 1.6727x over previous
#include <cuda_runtime.h>
#include <math.h>

#define TT 8192
#define AA 128
#define NB 128       // grid: one co-resident wave (< 148 SMs)
#define NT 512       // threads per block
#define NSQ 9        // squaring steps -> effective power 512 (proven converged)
#define NCH 16       // chain blocks (8 rows each), barrier group 1
#define SCB 16       // scalars block
#define NROLLB (NB - 17)   // 111 rolling blocks
#define STRIP 74     // windows per rolling block (111*74 >= 8182)

// ---------------- global scratch (static; no allocation) ----------------
__device__ float g_covpart[NB][AA*AA];   // 8.4 MB (L2-resident)
__device__ float g_colpart[NB][AA];
__device__ float g_diagpart[NB][AA];
__device__ float g_corr[AA*AA];
__device__ float g_eig0[AA*AA];
__device__ float g_eig1[AA*AA];
__device__ float g_rowsum[AA];
__device__ float g_rowabs[AA];
__device__ float g_rowsq[AA];
__device__ float g_fp[2][NCH];
__device__ float g_roll20[TT];
__device__ float g_roll10[TT];
__device__ float g_csstd[TT];
__device__ float g_conc[TT];
__device__ unsigned g_rolldone;
__device__ unsigned g_scaldone;

struct ScalarsT {
    double sum_cs, sum_conc, sum_r10, sum_last5, sum_rowsum, sum_rowabs, cnt20;
};
__device__ ScalarsT g_s;

// sense-reversal barriers: [0] = full grid (128), [1] = chain group (16)
__device__ unsigned g_bcnt[2];
__device__ unsigned g_bgen[2];

// ---------------- helpers ----------------
__device__ __forceinline__ float warpReduceAdd(float v) {
    #pragma unroll
    for (int o = 16; o; o >>= 1) v += __shfl_xor_sync(0xffffffffu, v, o);
    return v;
}

__device__ __forceinline__ void barrier_sync(int id, unsigned nb) {
    __syncthreads();
    if (threadIdx.x == 0) {
        __threadfence();
        volatile unsigned* genp = (volatile unsigned*)&g_bgen[id];
        unsigned g = *genp;
        unsigned old = atomicAdd(&g_bcnt[id], 1u);
        if (old == nb - 1u) {
            g_bcnt[id] = 0u;
            __threadfence();
            *genp = g + 1u;
        } else {
            while (*genp == g) { }   // L2 poll, no nanosleep
        }
        __threadfence();
    }
    __syncthreads();
}

__device__ __forceinline__ double blockReduceAddD(double v, double* sh) {
    int tid = threadIdx.x;
    sh[tid] = v; __syncthreads();
    for (int s = NT/2; s; s >>= 1) {
        if (tid < s) sh[tid] += sh[tid + s];
        __syncthreads();
    }
    double r = sh[0]; __syncthreads();
    return r;
}

// ---------------- rolling off-diag corr via C.sum = sum_t (sum_a z_a)^2 ----------------
// strip version: 16 warps x 5 windows over a 74-window strip
template<int W, int NWIN>
__device__ void roll_win_strip(const float* sh, int off, int lane, int wid, float* out) {
    for (int q = 0; q < 5; q++) {
        int lw = wid * 5 + q;              // warp-uniform
        if (lw >= STRIP) break;
        int widx = off + lw;
        if (widx >= NWIN) break;
        float S0=0,S1=0,S2=0,S3=0,Q0=0,Q1=0,Q2=0,Q3=0;
        #pragma unroll 5
        for (int t = 0; t < W; t++) {
            const float* row = sh + (lw + t) * AA + lane;
            float v0 = row[0], v1 = row[32], v2 = row[64], v3 = row[96];
            S0 += v0; Q0 = fmaf(v0, v0, Q0);
            S1 += v1; Q1 = fmaf(v1, v1, Q1);
            S2 += v2; Q2 = fmaf(v2, v2, Q2);
            S3 += v3; Q3 = fmaf(v3, v3, Q3);
        }
        const float iw = 1.0f / W;
        float i0 = rsqrtf(Q0 - S0*S0*iw);
        float i1 = rsqrtf(Q1 - S1*S1*iw);
        float i2 = rsqrtf(Q2 - S2*S2*iw);
        float i3 = rsqrtf(Q3 - S3*S3*iw);
        float part = S0*iw*i0 + S1*iw*i1 + S2*iw*i2 + S3*iw*i3;
        part = warpReduceAdd(part);        // sum_a mean_a * invd_a
        float acc = 0.f;
        #pragma unroll 5
        for (int t = 0; t < W; t++) {
            const float* row = sh + (lw + t) * AA + lane;
            float p = row[0]*i0 + row[32]*i1 + row[64]*i2 + row[96]*i3;
            p = warpReduceAdd(p);
            float s = p - part;            // sum_a z_a(t)
            acc = fmaf(s, s, acc);
        }
        if (lane == 0) out[widx] = (acc - (float)AA) * (1.0f/16256.0f);
    }
}

__device__ void roll_phase(const float* __restrict__ x, int b, float* SM,
                           int lane, int wid) {
    int tid = threadIdx.x;
    float* tile = SM;                      // 94 rows x 128 = 12032 floats (47 KB)
    int off = (b - 17) * STRIP;
    const float4* xv = reinterpret_cast<const float4*>(x);
    float4* tv = reinterpret_cast<float4*>(tile);
    #pragma unroll
    for (int it = 0; it < 6; it++) {
        int idx = tid + it * NT;
        if (idx < 94 * 32) {
            int gr = off + (idx >> 5);
            tv[idx] = (gr < TT) ? xv[(size_t)off * 32 + idx]
                                : make_float4(0.f, 0.f, 0.f, 0.f);
        }
    }
    __syncthreads();
    roll_win_strip<20, TT-20>(tile, off, lane, wid, g_roll20);
    roll_win_strip<10, TT-10>(tile, off, lane, wid, g_roll10);
}

// ---------------- one squaring step: out = (in . in) / ||in||_F^2 ----------------
// 16 blocks x 8 rows; 256 compute threads x 4 rows; double-buffered B staging
__device__ void square_step(int k, float* SM) {
    int tid = threadIdx.x;
    const float* in  = (k == 0) ? g_corr : (((k-1) & 1) ? g_eig1 : g_eig0);
    float*       out = (k & 1) ? g_eig1 : g_eig0;
    float* shrow = SM;             // 1024 floats: 8 A-rows
    float* bsh   = SM + 1024;      // 2 x 4096 floats: double-buffered 32-row chunks
    float* red   = SM + 9216;      // 80 floats scratch

    // Frobenius sum of input (warp 0)
    if (tid < 32) {
        float v;
        if (k == 0) v = g_rowsq[tid] + g_rowsq[tid+32] + g_rowsq[tid+64] + g_rowsq[tid+96];
        else        v = (tid < NCH) ? g_fp[(k-1) & 1][tid] : 0.f;
        v = warpReduceAdd(v);
        if (tid == 0) red[0] = v;
    }
    int r0 = blockIdx.x * 8;
    if (tid < 256) reinterpret_cast<float4*>(shrow)[tid] =
        reinterpret_cast<const float4*>(in + r0*AA)[tid];
    // preload chunk 0
    float4 pr0 = reinterpret_cast<const float4*>(in)[tid];
    float4 pr1 = reinterpret_cast<const float4*>(in)[tid + 512];
    reinterpret_cast<float4*>(bsh)[tid]       = pr0;
    reinterpret_cast<float4*>(bsh)[tid + 512] = pr1;
    __syncthreads();
    float s2 = 1.0f / red[0];

    int j = tid & 127, h = (tid >> 7) & 1;   // compute threads: tid < 256
    float a0 = 0.f, a1 = 0.f, a2 = 0.f, a3 = 0.f;
    int buf = 0;
    #pragma unroll
    for (int c = 0; c < 4; c++) {
        if (c < 3) {
            pr0 = reinterpret_cast<const float4*>(in + (c+1)*32*AA)[tid];
            pr1 = reinterpret_cast<const float4*>(in + (c+1)*32*AA)[tid + 512];
        }
        if (tid < 256) {
            const float* bp  = bsh + buf * 4096;
            const float* rp0 = shrow + (4*h + 0)*AA + c*32;
            const float* rp1 = shrow + (4*h + 1)*AA + c*32;
            const float* rp2 = shrow + (4*h + 2)*AA + c*32;
            const float* rp3 = shrow + (4*h + 3)*AA + c*32;
            #pragma unroll
            for (int k8 = 0; k8 < 8; k8++) {
                float4 av0 = *reinterpret_cast<const float4*>(rp0 + k8*4);
                float4 av1 = *reinterpret_cast<const float4*>(rp1 + k8*4);
                float4 av2 = *reinterpret_cast<const float4*>(rp2 + k8*4);
                float4 av3 = *reinterpret_cast<const float4*>(rp3 + k8*4);
                const float* bcol = bp + (k8*4)*AA + j;
                float b0 = bcol[0], b1 = bcol[AA], b2 = bcol[2*AA], b3 = bcol[3*AA];
                a0 = fmaf(av0.x, b0, a0); a1 = fmaf(av1.x, b0, a1);
                a2 = fmaf(av2.x, b0, a2); a3 = fmaf(av3.x, b0, a3);
                a0 = fmaf(av0.y, b1, a0); a1 = fmaf(av1.y, b1, a1);
                a2 = fmaf(av2.y, b1, a2); a3 = fmaf(av3.y, b1, a3);
                a0 = fmaf(av0.z, b2, a0); a1 = fmaf(av1.z, b2, a1);
                a2 = fmaf(av2.z, b2, a2); a3 = fmaf(av3.z, b2, a3);
                a0 = fmaf(av0.w, b3, a0); a1 = fmaf(av1.w, b3, a1);
                a2 = fmaf(av2.w, b3, a2); a3 = fmaf(av3.w, b3, a3);
            }
        }
        if (c < 3) {
            float4* dst = reinterpret_cast<float4*>(bsh + (buf ^ 1) * 4096);
            dst[tid] = pr0; dst[tid + 512] = pr1;
            __syncthreads();
            buf ^= 1;
        }
    }
    float ps = 0.f;
    if (tid < 256) {
        a0 *= s2; a1 *= s2; a2 *= s2; a3 *= s2;
        out[(r0 + 4*h + 0)*AA + j] = a0;
        out[(r0 + 4*h + 1)*AA + j] = a1;
        out[(r0 + 4*h + 2)*AA + j] = a2;
        out[(r0 + 4*h + 3)*AA + j] = a3;
        ps = a0*a0 + a1*a1 + a2*a2 + a3*a3;
    }
    ps = warpReduceAdd(ps);
    if ((tid & 31) == 0) red[16 + (tid >> 5)] = ps;
    __syncthreads();
    if (tid == 0) {
        float s = 0.f;
        #pragma unroll
        for (int w = 0; w < 16; w++) s += red[16 + w];
        g_fp[k & 1][blockIdx.x] = s;
    }
    __syncthreads();
}

// ---------------- fp64 scalar reductions (block 16) ----------------
__device__ void scalars_partA(float* SM) {
    double* sd = (double*)SM;
    int tid = threadIdx.x;
    double a;
    a = 0; for (int i = tid; i < TT; i += NT) a += (double)g_csstd[i];
    double sum_cs = blockReduceAddD(a, sd);
    a = 0; for (int i = tid; i < TT; i += NT) a += (double)g_conc[i];
    double sum_conc = blockReduceAddD(a, sd);
    a = (tid < AA) ? (double)g_rowsum[tid] : 0.0;
    double sum_rowsum = blockReduceAddD(a, sd);
    a = (tid < AA) ? (double)g_rowabs[tid] : 0.0;
    double sum_rowabs = blockReduceAddD(a, sd);
    if (tid == 0) {
        g_s.sum_cs = sum_cs; g_s.sum_conc = sum_conc;
        g_s.sum_rowsum = sum_rowsum; g_s.sum_rowabs = sum_rowabs;
    }
}

__device__ void scalars_partB(float* SM) {
    double* sd = (double*)SM;
    int tid = threadIdx.x;
    double a;
    a = 0; for (int i = tid; i < TT-20; i += NT) a += (g_roll20[i] > 0.7f) ? 1.0 : 0.0;
    double cnt20 = blockReduceAddD(a, sd);
    a = 0; for (int i = tid; i < TT-10; i += NT) a += (double)g_roll10[i];
    double sum_r10 = blockReduceAddD(a, sd);
    if (tid == 0) {
        double l5 = 0;
        for (int i = TT - 15; i < TT - 10; i++) l5 += (double)g_roll10[i];
        g_s.cnt20 = cnt20; g_s.sum_r10 = sum_r10; g_s.sum_last5 = l5;
    }
}

// ---------------- Rayleigh quotient + MLP + assembly (block 0) ----------------
__device__ void final_work(const float* x, const float* pos,
        const float* w1, const float* b1, const float* gam, const float* bet,
        const float* w2, const float* b2, const float* w3, const float* b3,
        float* out, float* SM) {
    int tid = threadIdx.x;
    float* feats = SM;                    // 256
    float* h1    = SM + 256;              // 128
    float* h2    = SM + 384;              // 64
    float* vvec  = SM + 448;              // 128
    float* rf    = SM + 576;              // 128
    int*   ri    = (int*)(SM + 704);      // 128
    double* rd   = (double*)(SM + 832);   // 128 doubles (byte 3328, 8-aligned)
    const float* Bf = ((NSQ - 1) & 1) ? g_eig1 : g_eig0;   // last step's output

    if (tid < 128) {
        feats[tid]       = x[(size_t)(TT-1)*AA + tid];
        feats[128 + tid] = pos[tid];
        rf[tid] = Bf[tid*AA + tid];
        ri[tid] = tid;
    }
    __syncthreads();
    for (int s = 64; s; s >>= 1) {
        if (tid < s && rf[tid+s] > rf[tid]) { rf[tid] = rf[tid+s]; ri[tid] = ri[tid+s]; }
        __syncthreads();
    }
    int jstar = ri[0];
    __syncthreads();
    if (tid < 128) vvec[tid] = Bf[jstar*AA + tid];
    __syncthreads();

    if (tid < 128) {
        float y = 0.f;
        #pragma unroll 4
        for (int k = 0; k < AA; k++) y = fmaf(g_corr[k*AA + tid], vvec[k], y);
        rd[tid] = (double)vvec[tid] * (double)y;
    }
    __syncthreads();
    for (int s = 64; s; s >>= 1) { if (tid < s) rd[tid] += rd[tid+s]; __syncthreads(); }
    double num = rd[0]; __syncthreads();
    if (tid < 128) rd[tid] = (double)vvec[tid] * (double)vvec[tid];
    __syncthreads();
    for (int s = 64; s; s >>= 1) { if (tid < s) rd[tid] += rd[tid+s]; __syncthreads(); }
    double den = rd[0]; __syncthreads();

    float pa = (tid < 128) ? fabsf(pos[tid]) : 0.f;
    if (tid < 128) rd[tid] = (double)pa;
    __syncthreads();
    for (int s = 64; s; s >>= 1) { if (tid < s) rd[tid] += rd[tid+s]; __syncthreads(); }
    double psum = rd[0]; __syncthreads();
    if (tid < 128) rf[tid] = pa;
    __syncthreads();
    for (int s = 64; s; s >>= 1) { if (tid < s) rf[tid] = fmaxf(rf[tid], rf[tid+s]); __syncthreads(); }
    float pmax = rf[0]; __syncthreads();

    // MLP (independent of g_s)
    if (tid < 128) {
        float s1 = b1[tid];
        #pragma unroll 4
        for (int k = 0; k < 2*AA; k++) s1 = fmaf(feats[k], w1[k*AA + tid], s1);
        s1 = fmaxf(s1, 0.f);
        const float bninv = 1.0f / sqrtf(1.0f + 1e-5f);
        h1[tid] = gam[tid] * (s1 * bninv) + bet[tid];
    }
    __syncthreads();
    if (tid < 64) {
        float s2v = b2[tid];
        #pragma unroll 4
        for (int k = 0; k < AA; k++) s2v = fmaf(h1[k], w2[k*64 + tid], s2v);
        h2[tid] = fmaxf(s2v, 0.f);
    }
    __syncthreads();

    // wait for scalars (block 16) before assembly
    if (tid == 0) {
        while (*(volatile unsigned*)&g_scaldone == 0u) { }
        __threadfence();
    }
    __syncthreads();

    if (tid == 0) {
        float lg[3];
        for (int c = 0; c < 3; c++) {
            float s = b3[c];
            for (int k = 0; k < 64; k++) s = fmaf(h2[k], w3[k*3 + c], s);
            lg[c] = s;
        }
        float m = fmaxf(lg[0], fmaxf(lg[1], lg[2]));
        float e0 = expf(lg[0]-m), e1 = expf(lg[1]-m), e2 = expf(lg[2]-m);
        float severity = e2 / (e0 + e1 + e2);

        float lam = (float)(num / den);
        float sync_ind = lam / (float)AA;
        float avg_corr = (float)(g_s.sum_rowsum / 16256.0);
        float sync_risk = fminf(1.0f, sync_ind * avg_corr);

        float cs0 = g_csstd[0], csl = g_csstd[TT-1];
        float avg_disp = (float)(g_s.sum_cs / (double)TT);
        float trend = (cs0 - csl) / (float)(TT - 1);
        float hi = fminf(fmaxf(trend / (avg_disp + 1e-6f) + 0.5f, 0.f), 1.f);

        float pl = (float)(g_s.cnt20 / (double)(TT - 20));

        float meanabs = (float)(g_s.sum_rowabs / ((double)AA * (double)AA));
        float retdiv = 1.0f - meanabs;
        float posdiv = 1.0f - pmax / (float)psum;
        float divloss = 1.0f - sqrtf(retdiv * posdiv);

        float hist = (float)((g_s.sum_r10 - g_s.sum_last5) / (double)(TT - 10 - 5));
        float rec  = (float)(g_s.sum_last5 / 5.0);
        float raw  = fminf(fmaxf((rec - hist) / hist, 0.f), 1.f);
        float surge = (hist > 0.f) ? raw : 0.f;

        float avgc = (float)((g_s.sum_conc / (double)TT - (double)AA) / 16256.0);
        float pc = fminf(fmaxf((avgc - 0.5f) * 2.0f, 0.f), 1.f);

        float coll = (hi + sync_risk + divloss) / 3.0f;

        out[0] = hi;      out[1] = severity; out[2] = sync_risk; out[3] = pl;
        out[4] = divloss; out[5] = surge;    out[6] = pc;        out[7] = coll;
    }
}

// ---------------- the single fused kernel ----------------
__global__ void __launch_bounds__(NT, 1)
fused_kernel(const float* __restrict__ x, const float* __restrict__ pos,
             const float* __restrict__ w1, const float* __restrict__ b1,
             const float* __restrict__ gam, const float* __restrict__ bet,
             const float* __restrict__ w2, const float* __restrict__ b2,
             const float* __restrict__ w3, const float* __restrict__ b3,
             float* __restrict__ out) {
    __shared__ __align__(16) float SM[12032];   // 47 KB, re-carved per phase
    int tid = threadIdx.x;
    int b = blockIdx.x;
    int wid = tid >> 5, lane = tid & 31;

    if (b == 0 && tid == 0) { g_rolldone = 0u; g_scaldone = 0u; }

    // ===== Phase A: 64-row tile; warps 0-7 Gram 8x8, warps 8-15 colsum+rowstats =====
    {
        float* tile = SM;    // 64x128 = 8192 floats
        int base = b * 64;
        const float4* xv = reinterpret_cast<const float4*>(x) + (size_t)base * 32;
        float4* tv = reinterpret_cast<float4*>(tile);
        #pragma unroll
        for (int it = 0; it < 4; it++) tv[tid + it * NT] = xv[tid + it * NT];
        __syncthreads();

        if (tid < 256) {
            // Gram partial: 16x16 tiles of 8x8 (LDS/FMA-balanced)
            int ti = tid >> 4, tj = tid & 15;
            int i0 = ti * 8, j0 = tj * 8;
            float acc[8][8] = {};
            for (int t = 0; t < 64; t++) {
                float a[8], bb8[8];
                *reinterpret_cast<float4*>(a)       = *reinterpret_cast<float4*>(&tile[t*AA + i0]);
                *reinterpret_cast<float4*>(a + 4)   = *reinterpret_cast<float4*>(&tile[t*AA + i0 + 4]);
                *reinterpret_cast<float4*>(bb8)     = *reinterpret_cast<float4*>(&tile[t*AA + j0]);
                *reinterpret_cast<float4*>(bb8 + 4) = *reinterpret_cast<float4*>(&tile[t*AA + j0 + 4]);
                #pragma unroll
                for (int ii = 0; ii < 8; ii++)
                    #pragma unroll
                    for (int jj = 0; jj < 8; jj++)
                        acc[ii][jj] = fmaf(a[ii], bb8[jj], acc[ii][jj]);
            }
            float* outp = g_covpart[b];
            #pragma unroll
            for (int ii = 0; ii < 8; ii++)
                #pragma unroll
                for (int jj = 0; jj < 8; jj++)
                    outp[(i0+ii)*AA + (j0+jj)] = acc[ii][jj];
            if (ti == tj) {
                #pragma unroll
                for (int ii = 0; ii < 8; ii++) g_diagpart[b][i0+ii] = acc[ii][ii];
            }
        } else {
            int t2 = tid - 256;
            if (t2 < 128) {
                float cs = 0.f;
                #pragma unroll 4
                for (int t = 0; t < 64; t++) cs += tile[t*AA + t2];
                g_colpart[b][t2] = cs;
            }
            // rowstats: warps 8-15, 8 rows each
            int w8 = wid - 8;
            #pragma unroll
            for (int q = 0; q < 8; q++) {
                int lr = w8 * 8 + q;
                int r = base + lr;
                float4 v = reinterpret_cast<float4*>(tile)[lr*32 + lane];
                float s = v.x + v.y + v.z + v.w;
                float qq = v.x*v.x + v.y*v.y + v.z*v.z + v.w*v.w;
                float p = ((v.x>0.f)?1.f:0.f)+((v.y>0.f)?1.f:0.f)+((v.z>0.f)?1.f:0.f)+((v.w>0.f)?1.f:0.f);
                float n = ((v.x<0.f)?1.f:0.f)+((v.y<0.f)?1.f:0.f)+((v.z<0.f)?1.f:0.f)+((v.w<0.f)?1.f:0.f);
                s = warpReduceAdd(s); qq = warpReduceAdd(qq);
                p = warpReduceAdd(p); n = warpReduceAdd(n);
                if (lane == 0) {
                    float var = (qq - s*s*(1.0f/AA)) * (1.0f/(AA-1));
                    g_csstd[r] = sqrtf(fmaxf(var, 0.f));
                    float z = (float)AA - p - n;
                    g_conc[r] = p*p + n*n + z*z;
                }
            }
        }
    }

    barrier_sync(0, NB);

    // ===== Phase B: corr row i = b, + row partials =====
    {
        float* colv = SM;           // 128
        float* invd = SM + 128;     // 128
        float* redA = SM + 256;     // 512
        float* redB = SM + 768;     // 512
        int jj = tid & 127, hh = tid >> 7;
        {
            float s = 0.f, d = 0.f;
            #pragma unroll 4
            for (int bb = hh*32; bb < hh*32 + 32; bb++) {
                s += g_colpart[bb][jj];
                d += g_diagpart[bb][jj];
            }
            redA[hh*128 + jj] = s;
            redB[hh*128 + jj] = d;
        }
        __syncthreads();
        if (tid < 128) {
            float s = redA[tid] + redA[128+tid] + redA[256+tid] + redA[384+tid];
            float d = redB[tid] + redB[128+tid] + redB[256+tid] + redB[384+tid];
            colv[tid] = s;
            invd[tid] = rsqrtf(d - s * s * (1.0f/TT));
        }
        __syncthreads();

        int i = b;
        float s = 0.f;
        #pragma unroll 4
        for (int bb = hh*32; bb < hh*32 + 32; bb++) s += g_covpart[bb][i*AA + jj];
        redA[hh*128 + jj] = s;
        __syncthreads();
        float c = 0.f;
        if (tid < 128) {
            float covij = redA[jj] + redA[128+jj] + redA[256+jj] + redA[384+jj];
            c = (covij - colv[i] * colv[jj] * (1.0f/TT)) * invd[i] * invd[jj];
            g_corr[i*AA + jj] = c;
        }
        __syncthreads();

        float coff = (tid < 128) ? ((jj == i) ? 0.f : c) : 0.f;
        float cab  = (tid < 128) ? fabsf(c) : 0.f;
        float csq  = (tid < 128) ? c*c : 0.f;
        coff = warpReduceAdd(coff);
        cab  = warpReduceAdd(cab);
        csq  = warpReduceAdd(csq);
        if (lane == 0) {
            redB[wid]      = coff;
            redB[16 + wid] = cab;
            redB[32 + wid] = csq;
        }
        __syncthreads();
        if (tid == 0) {
            float s0 = 0.f, s1 = 0.f, s2 = 0.f;
            #pragma unroll
            for (int w = 0; w < 16; w++) { s0 += redB[w]; s1 += redB[16+w]; s2 += redB[32+w]; }
            g_rowsum[i] = s0; g_rowabs[i] = s1; g_rowsq[i] = s2;
        }
    }

    barrier_sync(0, NB);

    // ===== Phase C: chain (0-15) || scalars (16) || rolling (17-127) =====
    if (b < NCH) {
        for (int k = 0; k < NSQ; k++) {
            square_step(k, SM);
            barrier_sync(1, NCH);
        }
        if (b == 0) final_work(x, pos, w1, b1, gam, bet, w2, b2, w3, b3, out, SM);
    } else if (b == SCB) {
        scalars_partA(SM);
        if (tid == 0) {
            while (*(volatile unsigned*)&g_rolldone != (unsigned)NROLLB) { }
            __threadfence();
        }
        __syncthreads();
        scalars_partB(SM);
        __syncthreads();
        if (tid == 0) {
            __threadfence();
            *(volatile unsigned*)&g_scaldone = 1u;
        }
    } else {
        roll_phase(x, b, SM, lane, wid);
        __syncthreads();
        if (tid == 0) {
            __threadfence();
            atomicAdd(&g_rolldone, 1u);
        }
    }
}

// ---------------- launch ----------------
extern "C" void kernel_launch(void* const* d_in, const int* in_sizes, int n_in,
                              void* d_out, int out_size) {
    const float* x    = (const float*)d_in[0];
    const float* pos  = (const float*)d_in[1];
    const float* w1   = (const float*)d_in[2];
    const float* b1   = (const float*)d_in[3];
    const float* gam  = (const float*)d_in[4];
    const float* bet  = (const float*)d_in[5];
    const float* w2   = (const float*)d_in[6];
    const float* b2   = (const float*)d_in[7];
    const float* w3   = (const float*)d_in[8];
    const float* b3   = (const float*)d_in[9];
    float* out = (float*)d_out;

    fused_kernel<<<NB, NT>>>(x, pos, w1, b1, gam, bet, w2, b2, w3, b3, out);
}

// round 15
// speedup vs baseline: 3.8952x; 1.2790x over previous
#include <cuda_runtime.h>
#include <math.h>

#define TT 8192
#define AA 128
#define NB 128       // grid: one co-resident wave (< 148 SMs)
#define NT 512       // threads per block
#define NSQ 9        // squaring steps -> effective power 512 (proven converged)
#define NCH 16       // chain blocks (8 rows each)
#define SCB 16       // scalars/MLP block
#define NROLLB (NB - 17)   // 111 rolling blocks
#define STRIP 74     // windows per rolling block (111*74 >= 8182)

// ---------------- global scratch (static; no allocation) ----------------
__device__ float g_covpart[NB][AA*AA];   // 8.4 MB (L2-resident)
__device__ float g_colpart[NB][AA];
__device__ float g_diagpart[NB][AA];
__device__ float g_corr[AA*AA];
__device__ float g_eig0[AA*AA];
__device__ float g_eig1[AA*AA];
__device__ float g_rowsum[AA];
__device__ float g_rowabs[AA];
__device__ float g_rowsq8[NCH];
__device__ float g_fp[2][NCH];
__device__ float g_roll20[TT];
__device__ float g_roll10[TT];
__device__ float g_csstd[TT];
__device__ float g_conc[TT];

struct ScalarsT {
    double sum_cs, sum_conc, sum_r10, sum_last5, sum_rowsum, sum_rowabs, cnt20;
    float sev, posdiv;
};
__device__ ScalarsT g_s;

// replay-safe sync state (all monotone or sense-reversal)
__device__ unsigned g_blkepoch[SCB + 1];   // per-block launch counters (blocks 0..16)
__device__ unsigned g_done[NCH];           // chain stage flags: ep*16 + stage
__device__ unsigned g_rolldone;            // accumulates NROLLB per launch
__device__ unsigned g_scaldone;            // set to ep when scalars complete
__device__ unsigned g_bcnt0, g_bgen0;      // arrival barrier (sense-reversal)

// ---------------- helpers ----------------
__device__ __forceinline__ float warpReduceAdd(float v) {
    #pragma unroll
    for (int o = 16; o; o >>= 1) v += __shfl_xor_sync(0xffffffffu, v, o);
    return v;
}

// all 128 blocks arrive; only blocks with wait=true poll for release
__device__ __forceinline__ void arrive0(bool wait) {
    __syncthreads();
    if (threadIdx.x == 0) {
        __threadfence();
        volatile unsigned* genp = (volatile unsigned*)&g_bgen0;
        unsigned g = *genp;
        unsigned old = atomicAdd(&g_bcnt0, 1u);
        if (old == NB - 1u) {
            g_bcnt0 = 0u;
            __threadfence();
            *genp = g + 1u;
        } else if (wait) {
            while (*genp == g) { }
        }
        __threadfence();
    }
    __syncthreads();
}

__device__ __forceinline__ void wait_done(unsigned tgt) {
    if (threadIdx.x < NCH) {
        while (*(volatile unsigned*)&g_done[threadIdx.x] < tgt) { }
    }
    __threadfence();
    __syncthreads();
}

__device__ __forceinline__ void set_done(int b, unsigned v) {
    __syncthreads();
    if (threadIdx.x == 0) {
        __threadfence();
        *(volatile unsigned*)&g_done[b] = v;
    }
}

__device__ __forceinline__ double blockReduceAddD(double v, double* sh) {
    int tid = threadIdx.x;
    sh[tid] = v; __syncthreads();
    for (int s = NT/2; s; s >>= 1) {
        if (tid < s) sh[tid] += sh[tid + s];
        __syncthreads();
    }
    double r = sh[0]; __syncthreads();
    return r;
}

// ---------------- rolling off-diag corr via C.sum = sum_t (sum_a z_a)^2 ----------------
template<int W, int NWIN>
__device__ void roll_win_strip(const float* sh, int off, int lane, int wid, float* out) {
    for (int q = 0; q < 5; q++) {
        int lw = wid * 5 + q;              // warp-uniform
        if (lw >= STRIP) break;
        int widx = off + lw;
        if (widx >= NWIN) break;
        float S0=0,S1=0,S2=0,S3=0,Q0=0,Q1=0,Q2=0,Q3=0;
        #pragma unroll 5
        for (int t = 0; t < W; t++) {
            const float* row = sh + (lw + t) * AA + lane;
            float v0 = row[0], v1 = row[32], v2 = row[64], v3 = row[96];
            S0 += v0; Q0 = fmaf(v0, v0, Q0);
            S1 += v1; Q1 = fmaf(v1, v1, Q1);
            S2 += v2; Q2 = fmaf(v2, v2, Q2);
            S3 += v3; Q3 = fmaf(v3, v3, Q3);
        }
        const float iw = 1.0f / W;
        float i0 = rsqrtf(Q0 - S0*S0*iw);
        float i1 = rsqrtf(Q1 - S1*S1*iw);
        float i2 = rsqrtf(Q2 - S2*S2*iw);
        float i3 = rsqrtf(Q3 - S3*S3*iw);
        float part = S0*iw*i0 + S1*iw*i1 + S2*iw*i2 + S3*iw*i3;
        part = warpReduceAdd(part);
        float acc = 0.f;
        #pragma unroll 5
        for (int t = 0; t < W; t++) {
            const float* row = sh + (lw + t) * AA + lane;
            float p = row[0]*i0 + row[32]*i1 + row[64]*i2 + row[96]*i3;
            p = warpReduceAdd(p);
            float s = p - part;
            acc = fmaf(s, s, acc);
        }
        if (lane == 0) out[widx] = (acc - (float)AA) * (1.0f/16256.0f);
    }
}

__device__ void roll_phase(const float* __restrict__ x, int b, float* SM,
                           int lane, int wid) {
    int tid = threadIdx.x;
    float* tile = SM;                      // 94 rows x 128
    int off = (b - 17) * STRIP;
    const float4* xv = reinterpret_cast<const float4*>(x);
    float4* tv = reinterpret_cast<float4*>(tile);
    #pragma unroll
    for (int it = 0; it < 6; it++) {
        int idx = tid + it * NT;
        if (idx < 94 * 32) {
            int gr = off + (idx >> 5);
            tv[idx] = (gr < TT) ? xv[(size_t)off * 32 + idx]
                                : make_float4(0.f, 0.f, 0.f, 0.f);
        }
    }
    __syncthreads();
    roll_win_strip<20, TT-20>(tile, off, lane, wid, g_roll20);
    roll_win_strip<10, TT-10>(tile, off, lane, wid, g_roll10);
}

// ---------------- chain: build corr rows 8b..8b+7 + row partials ----------------
__device__ void corr_phase(int b, float* SM) {
    int tid = threadIdx.x, lane = tid & 31, wid = tid >> 5;
    float* colv = SM;            // 128
    float* invd = SM + 128;      // 128
    float* red  = SM + 256;      // 1024
    int j = tid & 127, hh = tid >> 7;
    float s = 0.f, d = 0.f;
    #pragma unroll 4
    for (int bb = hh*32; bb < hh*32 + 32; bb++) {
        s += g_colpart[bb][j];
        d += g_diagpart[bb][j];
    }
    red[hh*128 + j] = s;
    red[512 + hh*128 + j] = d;
    __syncthreads();
    if (tid < 128) {
        float cs = red[tid] + red[128+tid] + red[256+tid] + red[384+tid];
        float dd = red[512+tid] + red[640+tid] + red[768+tid] + red[896+tid];
        colv[tid] = cs;
        invd[tid] = rsqrtf(dd - cs * cs * (1.0f/TT));
    }
    __syncthreads();

    int r = tid >> 6;                 // 0..7
    int c0 = (tid & 63) * 2;
    int row = b*8 + r;
    float ax = 0.f, ay = 0.f;
    #pragma unroll 8
    for (int bb = 0; bb < NB; bb++) {
        float2 v = *(const float2*)&g_covpart[bb][row*AA + c0];
        ax += v.x; ay += v.y;
    }
    float cvr = colv[row], ivr = invd[row];
    float cx = (ax - cvr * colv[c0]   * (1.0f/TT)) * ivr * invd[c0];
    float cy = (ay - cvr * colv[c0+1] * (1.0f/TT)) * ivr * invd[c0+1];
    *(float2*)&g_corr[row*AA + c0] = make_float2(cx, cy);

    float po = ((c0 == row) ? 0.f : cx) + ((c0+1 == row) ? 0.f : cy);
    float pa = fabsf(cx) + fabsf(cy);
    float pq = cx*cx + cy*cy;
    po = warpReduceAdd(po); pa = warpReduceAdd(pa); pq = warpReduceAdd(pq);
    __syncthreads();   // before red reuse
    if (lane == 0) { red[wid] = po; red[16+wid] = pa; red[32+wid] = pq; }
    __syncthreads();
    if (tid < 8) {
        g_rowsum[b*8 + tid] = red[2*tid] + red[2*tid+1];
        g_rowabs[b*8 + tid] = red[16 + 2*tid] + red[16 + 2*tid+1];
    }
    if (tid == 0) {
        float qs = 0.f;
        #pragma unroll
        for (int w = 0; w < 16; w++) qs += red[32 + w];
        g_rowsq8[b] = qs;
    }
}

// ---------------- one squaring step: out = (in . in) / ||in||_F^2 ----------------
__device__ void square_step(int k, float* SM) {
    int tid = threadIdx.x;
    const float* in  = (k == 0) ? g_corr : (((k-1) & 1) ? g_eig1 : g_eig0);
    float*       out = (k & 1) ? g_eig1 : g_eig0;
    float* shrow = SM;             // 1024: 8 A-rows
    float* bsh   = SM + 1024;      // 2 x 4096 double-buffered 32-row chunks
    float* red   = SM + 9216;      // scratch

    if (tid < 32) {
        float v = (tid < NCH) ? ((k == 0) ? g_rowsq8[tid] : g_fp[(k-1) & 1][tid]) : 0.f;
        v = warpReduceAdd(v);
        if (tid == 0) red[0] = v;
    }
    int r0 = blockIdx.x * 8;
    if (tid < 256) reinterpret_cast<float4*>(shrow)[tid] =
        reinterpret_cast<const float4*>(in + r0*AA)[tid];
    float4 pr0 = reinterpret_cast<const float4*>(in)[tid];
    float4 pr1 = reinterpret_cast<const float4*>(in)[tid + 512];
    reinterpret_cast<float4*>(bsh)[tid]       = pr0;
    reinterpret_cast<float4*>(bsh)[tid + 512] = pr1;
    __syncthreads();
    float s2 = 1.0f / red[0];

    int j = tid & 127, h = (tid >> 7) & 1;
    float a0 = 0.f, a1 = 0.f, a2 = 0.f, a3 = 0.f;
    int buf = 0;
    #pragma unroll
    for (int c = 0; c < 4; c++) {
        if (c < 3) {
            pr0 = reinterpret_cast<const float4*>(in + (c+1)*32*AA)[tid];
            pr1 = reinterpret_cast<const float4*>(in + (c+1)*32*AA)[tid + 512];
        }
        if (tid < 256) {
            const float* bp  = bsh + buf * 4096;
            const float* rp0 = shrow + (4*h + 0)*AA + c*32;
            const float* rp1 = shrow + (4*h + 1)*AA + c*32;
            const float* rp2 = shrow + (4*h + 2)*AA + c*32;
            const float* rp3 = shrow + (4*h + 3)*AA + c*32;
            #pragma unroll
            for (int k8 = 0; k8 < 8; k8++) {
                float4 av0 = *reinterpret_cast<const float4*>(rp0 + k8*4);
                float4 av1 = *reinterpret_cast<const float4*>(rp1 + k8*4);
                float4 av2 = *reinterpret_cast<const float4*>(rp2 + k8*4);
                float4 av3 = *reinterpret_cast<const float4*>(rp3 + k8*4);
                const float* bcol = bp + (k8*4)*AA + j;
                float b0 = bcol[0], b1 = bcol[AA], b2 = bcol[2*AA], b3 = bcol[3*AA];
                a0 = fmaf(av0.x, b0, a0); a1 = fmaf(av1.x, b0, a1);
                a2 = fmaf(av2.x, b0, a2); a3 = fmaf(av3.x, b0, a3);
                a0 = fmaf(av0.y, b1, a0); a1 = fmaf(av1.y, b1, a1);
                a2 = fmaf(av2.y, b1, a2); a3 = fmaf(av3.y, b1, a3);
                a0 = fmaf(av0.z, b2, a0); a1 = fmaf(av1.z, b2, a1);
                a2 = fmaf(av2.z, b2, a2); a3 = fmaf(av3.z, b2, a3);
                a0 = fmaf(av0.w, b3, a0); a1 = fmaf(av1.w, b3, a1);
                a2 = fmaf(av2.w, b3, a2); a3 = fmaf(av3.w, b3, a3);
            }
        }
        if (c < 3) {
            float4* dst = reinterpret_cast<float4*>(bsh + (buf ^ 1) * 4096);
            dst[tid] = pr0; dst[tid + 512] = pr1;
            __syncthreads();
            buf ^= 1;
        }
    }
    float ps = 0.f;
    if (tid < 256) {
        a0 *= s2; a1 *= s2; a2 *= s2; a3 *= s2;
        out[(r0 + 4*h + 0)*AA + j] = a0;
        out[(r0 + 4*h + 1)*AA + j] = a1;
        out[(r0 + 4*h + 2)*AA + j] = a2;
        out[(r0 + 4*h + 3)*AA + j] = a3;
        ps = a0*a0 + a1*a1 + a2*a2 + a3*a3;
    }
    ps = warpReduceAdd(ps);
    if ((tid & 31) == 0) red[16 + (tid >> 5)] = ps;
    __syncthreads();
    if (tid == 0) {
        float s = 0.f;
        #pragma unroll
        for (int w = 0; w < 16; w++) s += red[16 + w];
        g_fp[k & 1][blockIdx.x] = s;
    }
}

// ---------------- block 16: MLP severity + position diversity ----------------
__device__ void mlp_posdiv(const float* x, const float* pos,
        const float* w1, const float* b1, const float* gam, const float* bet,
        const float* w2, const float* b2, const float* w3, const float* b3,
        float* SM) {
    int tid = threadIdx.x;
    float* feats = SM;                    // 256
    float* h1    = SM + 256;              // 128
    float* h2    = SM + 384;              // 64
    double* rd   = (double*)(SM + 448);   // 128 doubles (byte 1792, 8-aligned)
    float* rf    = SM + 704;              // 128

    if (tid < 128) {
        feats[tid]       = x[(size_t)(TT-1)*AA + tid];
        feats[128 + tid] = pos[tid];
    }
    __syncthreads();
    if (tid < 128) {
        float s1 = b1[tid];
        #pragma unroll 4
        for (int k = 0; k < 2*AA; k++) s1 = fmaf(feats[k], w1[k*AA + tid], s1);
        s1 = fmaxf(s1, 0.f);
        const float bninv = 1.0f / sqrtf(1.0f + 1e-5f);
        h1[tid] = gam[tid] * (s1 * bninv) + bet[tid];
    }
    __syncthreads();
    if (tid < 64) {
        float s2v = b2[tid];
        #pragma unroll 4
        for (int k = 0; k < AA; k++) s2v = fmaf(h1[k], w2[k*64 + tid], s2v);
        h2[tid] = fmaxf(s2v, 0.f);
    }
    float pa = (tid < 128) ? fabsf(pos[tid]) : 0.f;
    if (tid < 128) { rd[tid] = (double)pa; rf[tid] = pa; }
    __syncthreads();
    for (int s = 64; s; s >>= 1) {
        if (tid < s) { rd[tid] += rd[tid+s]; rf[tid] = fmaxf(rf[tid], rf[tid+s]); }
        __syncthreads();
    }
    if (tid == 0) {
        double psum = rd[0];
        float pmax = rf[0];
        float lg[3];
        for (int c = 0; c < 3; c++) {
            float s = b3[c];
            for (int k = 0; k < 64; k++) s = fmaf(h2[k], w3[k*3 + c], s);
            lg[c] = s;
        }
        float m = fmaxf(lg[0], fmaxf(lg[1], lg[2]));
        float e0 = expf(lg[0]-m), e1 = expf(lg[1]-m), e2 = expf(lg[2]-m);
        g_s.sev = e2 / (e0 + e1 + e2);
        g_s.posdiv = 1.0f - pmax / (float)psum;
    }
    __syncthreads();
}

// ---------------- block 16 scalar reductions ----------------
__device__ void scalars_A1(float* SM) {
    double* sd = (double*)SM;
    int tid = threadIdx.x;
    double a;
    a = 0; for (int i = tid; i < TT; i += NT) a += (double)g_csstd[i];
    double sum_cs = blockReduceAddD(a, sd);
    a = 0; for (int i = tid; i < TT; i += NT) a += (double)g_conc[i];
    double sum_conc = blockReduceAddD(a, sd);
    if (tid == 0) { g_s.sum_cs = sum_cs; g_s.sum_conc = sum_conc; }
}
__device__ void scalars_A2(float* SM) {
    double* sd = (double*)SM;
    int tid = threadIdx.x;
    double a;
    a = (tid < AA) ? (double)g_rowsum[tid] : 0.0;
    double sum_rowsum = blockReduceAddD(a, sd);
    a = (tid < AA) ? (double)g_rowabs[tid] : 0.0;
    double sum_rowabs = blockReduceAddD(a, sd);
    if (tid == 0) { g_s.sum_rowsum = sum_rowsum; g_s.sum_rowabs = sum_rowabs; }
}
__device__ void scalars_B(float* SM) {
    double* sd = (double*)SM;
    int tid = threadIdx.x;
    double a;
    a = 0; for (int i = tid; i < TT-20; i += NT) a += (g_roll20[i] > 0.7f) ? 1.0 : 0.0;
    double cnt20 = blockReduceAddD(a, sd);
    a = 0; for (int i = tid; i < TT-10; i += NT) a += (double)g_roll10[i];
    double sum_r10 = blockReduceAddD(a, sd);
    if (tid == 0) {
        double l5 = 0;
        for (int i = TT - 15; i < TT - 10; i++) l5 += (double)g_roll10[i];
        g_s.cnt20 = cnt20; g_s.sum_r10 = sum_r10; g_s.sum_last5 = l5;
    }
}

// ---------------- block 0: Rayleigh quotient + assembly ----------------
__device__ void final_work(float* out, float* SM, unsigned ep) {
    int tid = threadIdx.x;
    float* vvec = SM;                     // 128
    float* rf   = SM + 128;               // 128
    int*   ri   = (int*)(SM + 256);       // 128
    double* rd  = (double*)(SM + 384);    // 128 doubles (byte 1536, 8-aligned)
    const float* Bf = ((NSQ - 1) & 1) ? g_eig1 : g_eig0;

    if (tid < 128) { rf[tid] = Bf[tid*AA + tid]; ri[tid] = tid; }
    __syncthreads();
    for (int s = 64; s; s >>= 1) {
        if (tid < s && rf[tid+s] > rf[tid]) { rf[tid] = rf[tid+s]; ri[tid] = ri[tid+s]; }
        __syncthreads();
    }
    int jstar = ri[0];
    __syncthreads();
    if (tid < 128) vvec[tid] = Bf[jstar*AA + tid];
    __syncthreads();
    if (tid < 128) {
        float y = 0.f;
        #pragma unroll 4
        for (int k = 0; k < AA; k++) y = fmaf(g_corr[k*AA + tid], vvec[k], y);
        rd[tid] = (double)vvec[tid] * (double)y;
    }
    __syncthreads();
    for (int s = 64; s; s >>= 1) { if (tid < s) rd[tid] += rd[tid+s]; __syncthreads(); }
    double num = rd[0]; __syncthreads();
    if (tid < 128) rd[tid] = (double)vvec[tid] * (double)vvec[tid];
    __syncthreads();
    for (int s = 64; s; s >>= 1) { if (tid < s) rd[tid] += rd[tid+s]; __syncthreads(); }
    double den = rd[0];

    if (tid == 0) {
        while (*(volatile unsigned*)&g_scaldone < ep) { }
        __threadfence();

        float lam = (float)(num / den);
        float sync_ind = lam / (float)AA;
        float avg_corr = (float)(g_s.sum_rowsum / 16256.0);
        float sync_risk = fminf(1.0f, sync_ind * avg_corr);

        float cs0 = g_csstd[0], csl = g_csstd[TT-1];
        float avg_disp = (float)(g_s.sum_cs / (double)TT);
        float trend = (cs0 - csl) / (float)(TT - 1);
        float hi = fminf(fmaxf(trend / (avg_disp + 1e-6f) + 0.5f, 0.f), 1.f);

        float pl = (float)(g_s.cnt20 / (double)(TT - 20));

        float meanabs = (float)(g_s.sum_rowabs / ((double)AA * (double)AA));
        float retdiv = 1.0f - meanabs;
        float divloss = 1.0f - sqrtf(retdiv * g_s.posdiv);

        float hist = (float)((g_s.sum_r10 - g_s.sum_last5) / (double)(TT - 10 - 5));
        float rec  = (float)(g_s.sum_last5 / 5.0);
        float raw  = fminf(fmaxf((rec - hist) / hist, 0.f), 1.f);
        float surge = (hist > 0.f) ? raw : 0.f;

        float avgc = (float)((g_s.sum_conc / (double)TT - (double)AA) / 16256.0);
        float pc = fminf(fmaxf((avgc - 0.5f) * 2.0f, 0.f), 1.f);

        float coll = (hi + sync_risk + divloss) / 3.0f;

        out[0] = hi;      out[1] = g_s.sev; out[2] = sync_risk; out[3] = pl;
        out[4] = divloss; out[5] = surge;   out[6] = pc;        out[7] = coll;
    }
}

// ---------------- the single fused kernel ----------------
__global__ void __launch_bounds__(NT, 1)
fused_kernel(const float* __restrict__ x, const float* __restrict__ pos,
             const float* __restrict__ w1, const float* __restrict__ b1,
             const float* __restrict__ gam, const float* __restrict__ bet,
             const float* __restrict__ w2, const float* __restrict__ b2,
             const float* __restrict__ w3, const float* __restrict__ b3,
             float* __restrict__ out) {
    __shared__ __align__(16) float SM[12032];   // 47 KB, re-carved per phase
    __shared__ unsigned sh_ep;
    int tid = threadIdx.x;
    int b = blockIdx.x;
    int wid = tid >> 5, lane = tid & 31;

    if (b <= SCB && tid == 0) sh_ep = atomicAdd(&g_blkepoch[b], 1u) + 1u;

    // ===== Phase A: 64-row tile; symmetric Gram + colsum + rowstats =====
    {
        float* tile = SM;    // 64x128 = 8192 floats
        int base = b * 64;
        const float4* xv = reinterpret_cast<const float4*>(x) + (size_t)base * 32;
        float4* tv = reinterpret_cast<float4*>(tile);
        #pragma unroll
        for (int it = 0; it < 4; it++) tv[tid + it * NT] = xv[tid + it * NT];
        __syncthreads();

        if (tid < 128) {
            // 128 lower-triangle 8x8 tiles: l = ti*(ti+1)/2 + tj (covers ti 0..14 full + (15, 0..7))
            int ti = (int)((sqrtf(8.f*(float)tid + 1.f) - 1.f) * 0.5f);
            while ((ti+1)*(ti+2)/2 <= tid) ti++;
            while (ti*(ti+1)/2 > tid) ti--;
            int tj = tid - ti*(ti+1)/2;
            int i0 = ti * 8, j0 = tj * 8;
            float acc[8][8] = {};
            for (int t = 0; t < 64; t++) {
                float a[8], bb8[8];
                *reinterpret_cast<float4*>(a)       = *reinterpret_cast<float4*>(&tile[t*AA + i0]);
                *reinterpret_cast<float4*>(a + 4)   = *reinterpret_cast<float4*>(&tile[t*AA + i0 + 4]);
                *reinterpret_cast<float4*>(bb8)     = *reinterpret_cast<float4*>(&tile[t*AA + j0]);
                *reinterpret_cast<float4*>(bb8 + 4) = *reinterpret_cast<float4*>(&tile[t*AA + j0 + 4]);
                #pragma unroll
                for (int ii = 0; ii < 8; ii++)
                    #pragma unroll
                    for (int jj = 0; jj < 8; jj++)
                        acc[ii][jj] = fmaf(a[ii], bb8[jj], acc[ii][jj]);
            }
            float* outp = g_covpart[b];
            #pragma unroll
            for (int ii = 0; ii < 8; ii++)
                #pragma unroll
                for (int jj = 0; jj < 8; jj++)
                    outp[(i0+ii)*AA + (j0+jj)] = acc[ii][jj];
            if (ti != tj) {
                #pragma unroll
                for (int ii = 0; ii < 8; ii++)
                    #pragma unroll
                    for (int jj = 0; jj < 8; jj++)
                        outp[(j0+jj)*AA + (i0+ii)] = acc[ii][jj];
            } else {
                #pragma unroll
                for (int ii = 0; ii < 8; ii++) g_diagpart[b][i0+ii] = acc[ii][ii];
            }
        } else if (tid < 160) {
            // warp 4: strip rows 120..127 x cols 64..127 as 2x8 micro-tiles
            int l = tid - 128;
            int i0 = 120 + 2 * (l >> 3);
            int j0 = 64 + 8 * (l & 7);
            float acc[2][8] = {};
            for (int t = 0; t < 64; t++) {
                float2 a2 = *reinterpret_cast<float2*>(&tile[t*AA + i0]);
                float bb8[8];
                *reinterpret_cast<float4*>(bb8)     = *reinterpret_cast<float4*>(&tile[t*AA + j0]);
                *reinterpret_cast<float4*>(bb8 + 4) = *reinterpret_cast<float4*>(&tile[t*AA + j0 + 4]);
                #pragma unroll
                for (int jj = 0; jj < 8; jj++) {
                    acc[0][jj] = fmaf(a2.x, bb8[jj], acc[0][jj]);
                    acc[1][jj] = fmaf(a2.y, bb8[jj], acc[1][jj]);
                }
            }
            float* outp = g_covpart[b];
            #pragma unroll
            for (int ii = 0; ii < 2; ii++)
                #pragma unroll
                for (int jj = 0; jj < 8; jj++) {
                    int gi = i0 + ii, gj = j0 + jj;
                    outp[gi*AA + gj] = acc[ii][jj];
                    outp[gj*AA + gi] = acc[ii][jj];   // duplicate on diag region: same value
                    if (gi == gj) g_diagpart[b][gi] = acc[ii][jj];
                }
        } else if (tid < 416) {
            // rowstats: warps 5..12, 8 rows each
            int w8 = wid - 5;
            #pragma unroll
            for (int q = 0; q < 8; q++) {
                int lr = w8 * 8 + q;
                int r = base + lr;
                float4 v = reinterpret_cast<float4*>(tile)[lr*32 + lane];
                float s = v.x + v.y + v.z + v.w;
                float qq = v.x*v.x + v.y*v.y + v.z*v.z + v.w*v.w;
                float p = ((v.x>0.f)?1.f:0.f)+((v.y>0.f)?1.f:0.f)+((v.z>0.f)?1.f:0.f)+((v.w>0.f)?1.f:0.f);
                float n = ((v.x<0.f)?1.f:0.f)+((v.y<0.f)?1.f:0.f)+((v.z<0.f)?1.f:0.f)+((v.w<0.f)?1.f:0.f);
                s = warpReduceAdd(s); qq = warpReduceAdd(qq);
                p = warpReduceAdd(p); n = warpReduceAdd(n);
                if (lane == 0) {
                    float var = (qq - s*s*(1.0f/AA)) * (1.0f/(AA-1));
                    g_csstd[r] = sqrtf(fmaxf(var, 0.f));
                    float z = (float)AA - p - n;
                    g_conc[r] = p*p + n*n + z*z;
                }
            }
        } else {
            // colsum: warps 13..15 (96 threads)
            int t3 = tid - 416;
            float cs = 0.f;
            #pragma unroll 4
            for (int t = 0; t < 64; t++) cs += tile[t*AA + t3];
            g_colpart[b][t3] = cs;
            if (t3 < 32) {
                int c = t3 + 96;
                float cs2 = 0.f;
                #pragma unroll 4
                for (int t = 0; t < 64; t++) cs2 += tile[t*AA + c];
                g_colpart[b][c] = cs2;
            }
        }
    }

    arrive0(b <= SCB);   // rolling blocks arrive and proceed immediately

    if (b < NCH) {
        unsigned ep16 = sh_ep * 16u;
        corr_phase(b, SM);
        set_done(b, ep16 + 1u);
        for (int k = 0; k < NSQ; k++) {
            wait_done(ep16 + (unsigned)k + 1u);
            square_step(k, SM);
            set_done(b, ep16 + (unsigned)k + 2u);
        }
        if (b == 0) {
            wait_done(ep16 + (unsigned)NSQ + 1u);
            final_work(out, SM, sh_ep);
        }
    } else if (b == SCB) {
        unsigned ep = sh_ep;
        mlp_posdiv(x, pos, w1, b1, gam, bet, w2, b2, w3, b3, SM);
        scalars_A1(SM);
        wait_done(ep * 16u + 1u);
        scalars_A2(SM);
        if (tid == 0) {
            while (*(volatile unsigned*)&g_rolldone < ep * (unsigned)NROLLB) { }
            __threadfence();
        }
        __syncthreads();
        scalars_B(SM);
        __syncthreads();
        if (tid == 0) {
            __threadfence();
            *(volatile unsigned*)&g_scaldone = ep;
        }
    } else {
        roll_phase(x, b, SM, lane, wid);
        __syncthreads();
        if (tid == 0) {
            __threadfence();
            atomicAdd(&g_rolldone, 1u);
        }
    }
}

// ---------------- launch ----------------
extern "C" void kernel_launch(void* const* d_in, const int* in_sizes, int n_in,
                              void* d_out, int out_size) {
    const float* x    = (const float*)d_in[0];
    const float* pos  = (const float*)d_in[1];
    const float* w1   = (const float*)d_in[2];
    const float* b1   = (const float*)d_in[3];
    const float* gam  = (const float*)d_in[4];
    const float* bet  = (const float*)d_in[5];
    const float* w2   = (const float*)d_in[6];
    const float* b2   = (const float*)d_in[7];
    const float* w3   = (const float*)d_in[8];
    const float* b3   = (const float*)d_in[9];
    float* out = (float*)d_out;

    fused_kernel<<<NB, NT>>>(x, pos, w1, b1, gam, bet, w2, b2, w3, b3, out);
}